// round 13
// baseline (speedup 1.0000x reference)
#include <cuda_runtime.h>
#include <cuda.h>
#include <cstdint>

// ---------------------------------------------------------------------------
// BBoxHead via manual tf32 mma.sync GEMMs, TMA-fed, warp-specialized.
// CTA 128x128, 8 consumer warps (32x64) + 1 TMA producer, 5-stage pipeline.
// Operands k-permuted within k8 groups ([0,4,1,5,2,6,3,7]) -> ld.shared.v2.
// A pre-rounded (rna) in prep/BN passes; B transposed+rna in prep.
// Heads GEMM writes logits/deltas directly (scatter fused).
// ---------------------------------------------------------------------------

#define N_ROI  2000
#define K1     12544
#define HID    1024
#define NCLS   81
#define NDEL   324
#define NHEAD  405
#define NHPAD  512
#define BN_EPS 1e-3f

#define POS(j) (((j) < 4) ? 2 * (j) : 2 * ((j) - 4) + 1)

__device__ float g_Ap  [N_ROI * K1];
__device__ float g_W1t [HID * K1];
__device__ float g_W2t [HID * HID];
__device__ float g_Wht [NHPAD * HID];
__device__ float g_bh  [NHPAD];
__device__ float g_x1  [2048 * HID];
__device__ float g_x1p [2048 * HID];
__device__ float g_x2  [2048 * HID];
__device__ float g_x2p [2048 * HID];
__device__ float g_scale[HID];
__device__ float g_shift[HID];

// ---------------------------------------------------------------------------
__device__ __forceinline__ uint32_t smem_u32(const void* p) {
    uint32_t a;
    asm("{ .reg .u64 t; cvta.to.shared.u64 t, %1; cvt.u32.u64 %0, t; }" : "=r"(a) : "l"(p));
    return a;
}
__device__ __forceinline__ float rna_tf32(float x) {
    uint32_t r;
    asm("cvt.rna.tf32.f32 %0, %1;" : "=r"(r) : "f"(x));
    return __uint_as_float(r);
}

#define MBAR_INIT(a, c)      asm volatile("mbarrier.init.shared.b64 [%0], %1;" :: "r"(a), "r"(c) : "memory")
#define MBAR_EXPECT_TX(a, b) asm volatile("mbarrier.arrive.expect_tx.shared.b64 _, [%0], %1;" :: "r"(a), "r"(b) : "memory")
#define MBAR_ARRIVE(a)       asm volatile("mbarrier.arrive.shared.b64 _, [%0];" :: "r"(a) : "memory")
#define MBAR_WAIT(a, ph) do {                                                     \
    uint32_t _m = (a); uint32_t _p = (ph);                                        \
    asm volatile("{\n\t.reg .pred P;\n\t"                                         \
        "WL_%=:\n\t"                                                              \
        "mbarrier.try_wait.parity.acquire.cta.shared::cta.b64 P, [%0], %1, 0x989680;\n\t" \
        "@P bra.uni WD_%=;\n\t"                                                   \
        "bra.uni WL_%=;\n\t"                                                      \
        "WD_%=:\n\t}" :: "r"(_m), "r"(_p) : "memory");                            \
} while (0)

#define TMA_LOAD_2D(saddr, mp, cx, cy, mb)                                        \
    asm volatile("cp.async.bulk.tensor.2d.shared::cta.global.tile.mbarrier::complete_tx::bytes " \
                 "[%0], [%1, {%2, %3}], [%4];"                                    \
                 :: "r"(saddr), "l"(mp), "r"(cx), "r"(cy), "r"(mb) : "memory")

#define LD2(r0, r1, addr)                                                         \
    asm volatile("ld.shared.v2.b32 {%0,%1}, [%2];" : "=r"(r0), "=r"(r1) : "r"(addr))

#define ST2(addr, v0, v1)                                                         \
    asm volatile("st.shared.v2.f32 [%0], {%1,%2};" :: "r"(addr), "f"(v0), "f"(v1) : "memory")

#define MMA(cr, A0, A1, A2, A3, B0, B1)                                           \
    asm volatile("mma.sync.aligned.m16n8k8.row.col.f32.tf32.tf32.f32 "            \
        "{%0,%1,%2,%3}, {%4,%5,%6,%7}, {%8,%9}, {%0,%1,%2,%3};"                   \
        : "+f"((cr)[0]), "+f"((cr)[1]), "+f"((cr)[2]), "+f"((cr)[3])              \
        : "r"(A0), "r"(A1), "r"(A2), "r"(A3), "r"(B0), "r"(B1))

// ---------------------------------------------------------------------------
#define LDT      40
#define TM       128
#define TN       128
#define TILE_A   (TM * LDT * 4)                   // 20480
#define STAGE_B  (2 * TILE_A)                     // 40960
#define NSTAGE   5
#define SM_TILE0 1024
#define SMEM_TOT (SM_TILE0 + NSTAGE * STAGE_B)    // 205824
#define TXBYTES  STAGE_B
#define LDE      132
#define NTHREADS 288

__global__ __launch_bounds__(NTHREADS)
void gemm_tf32_tma(const __grid_constant__ CUtensorMap mapA,
                   const __grid_constant__ CUtensorMap mapB,
                   const float* __restrict__ bias, float* __restrict__ C,
                   float* __restrict__ hd_logits, float* __restrict__ hd_deltas,
                   int M, int K, int ldC) {
    extern __shared__ float smem_f[];
    const uint32_t sb = smem_u32(smem_f);
    const int tid  = threadIdx.x;
    const int wid  = tid >> 5;
    const int lane = tid & 31;
    const int row0 = blockIdx.y * TM;
    const int col0 = blockIdx.x * TN;
    const int NK = K / 32;

    if (tid == 0) {
#pragma unroll
        for (int s = 0; s < NSTAGE; s++) {
            MBAR_INIT(sb + s * 16,     1);
            MBAR_INIT(sb + s * 16 + 8, 8);
        }
    }
    __syncthreads();

    const int warp_m = wid & 3;
    const int warp_n = wid >> 2;
    const int g = lane >> 2;
    const int t = lane & 3;

    float c0[8][4], c1[8][4];

    if (wid == 8) {
        if (lane == 0) {
            int s = 0, ph = 1;
            for (int i = 0; i < NK; i++) {
                MBAR_WAIT(sb + s * 16 + 8, ph);
                uint32_t st = sb + SM_TILE0 + s * STAGE_B;
                MBAR_EXPECT_TX(sb + s * 16, TXBYTES);
                TMA_LOAD_2D(st,          &mapA, i * 32, row0, sb + s * 16);
                TMA_LOAD_2D(st + TILE_A, &mapB, i * 32, col0, sb + s * 16);
                if (++s == NSTAGE) { s = 0; ph ^= 1; }
            }
        }
    } else {
#pragma unroll
        for (int nj = 0; nj < 8; nj++)
#pragma unroll
            for (int r = 0; r < 4; r++) { c0[nj][r] = 0.f; c1[nj][r] = 0.f; }

        const uint32_t aLane = ((warp_m * 32 + g) * LDT + 2 * t) * 4;
        const uint32_t bLane = ((warp_n * 64 + g) * LDT + 2 * t) * 4;

        int s = 0, ph = 0;
        for (int i = 0; i < NK; i++) {
            MBAR_WAIT(sb + s * 16, ph);
            const uint32_t sA = sb + SM_TILE0 + s * STAGE_B + aLane;
            const uint32_t sB = sb + SM_TILE0 + s * STAGE_B + TILE_A + bLane;

#pragma unroll
            for (int ks = 0; ks < 4; ks++) {
                const uint32_t ko = ks * 32;
                uint32_t A0, A1, A2, A3, A4, A5, A6, A7;
                LD2(A0, A2, sA + ko);
                LD2(A1, A3, sA + 8  * LDT * 4 + ko);
                LD2(A4, A6, sA + 16 * LDT * 4 + ko);
                LD2(A5, A7, sA + 24 * LDT * 4 + ko);
                // interleave B fragment loads with MMAs to shorten the
                // post-load critical path (ptxas keeps the overlap).
#pragma unroll
                for (int nj = 0; nj < 8; nj++) {
                    uint32_t B0, B1;
                    LD2(B0, B1, sB + nj * 8 * LDT * 4 + ko);
                    MMA(c0[nj], A0, A1, A2, A3, B0, B1);
                    MMA(c1[nj], A4, A5, A6, A7, B0, B1);
                }
            }

            if (lane == 0) MBAR_ARRIVE(sb + s * 16 + 8);
            if (++s == NSTAGE) { s = 0; ph ^= 1; }
        }
    }
    __syncthreads();

    if (wid != 8) {
        const uint32_t eb = sb;
#pragma unroll
        for (int nj = 0; nj < 8; nj++) {
            uint32_t colb = (warp_n * 64 + nj * 8 + 2 * t) * 4;
            uint32_t r0 = (warp_m * 32 + g) * LDE * 4;
            ST2(eb + r0 + colb,                c0[nj][0], c0[nj][1]);
            ST2(eb + r0 + 8  * LDE * 4 + colb, c0[nj][2], c0[nj][3]);
            ST2(eb + r0 + 16 * LDE * 4 + colb, c1[nj][0], c1[nj][1]);
            ST2(eb + r0 + 24 * LDE * 4 + colb, c1[nj][2], c1[nj][3]);
        }
    }
    __syncthreads();

    const float* esm = smem_f;
    if (hd_deltas == nullptr) {
#pragma unroll 2
        for (int e = tid; e < TM * 32; e += NTHREADS) {
            int r  = e >> 5;
            int c4 = (e & 31) * 4;
            int gr = row0 + r;
            if (gr < M) {
                const float* sp = esm + r * LDE + c4;
                float4 v;
                v.x = sp[0] + bias[col0 + c4 + 0];
                v.y = sp[1] + bias[col0 + c4 + 1];
                v.z = sp[2] + bias[col0 + c4 + 2];
                v.w = sp[3] + bias[col0 + c4 + 3];
                *(float4*)&C[(size_t)gr * ldC + col0 + c4] = v;
            }
        }
    } else {
        // heads epilogue: write logits / deltas directly
        for (int e = tid; e < TM * TN; e += NTHREADS) {
            int r  = e >> 7;            // 0..127
            int c  = e & 127;
            int gr = row0 + r;
            int gc = col0 + c;
            if (gr < M && gc < NHEAD) {
                float v = esm[r * LDE + c] + bias[gc];
                if (gc < NCLS) hd_logits[(size_t)gr * NCLS + gc] = v;
                else           hd_deltas[(size_t)gr * NDEL + (gc - NCLS)] = v;
            }
        }
    }
}

// ---------------------------------------------------------------------------
// Prep kernels
// ---------------------------------------------------------------------------
// rna + k8-permute, 8 floats per thread (2x float4 in, 2x float4 out).
// out group = interleave(lo, hi): {l0,h0,l1,h1} {l2,h2,l3,h3}
__global__ void cvt_rna_permute8(const float* __restrict__ in, float* __restrict__ out,
                                 int n8) {
    int i = blockIdx.x * blockDim.x + threadIdx.x;
    if (i < n8) {
        float4 lo = ((const float4*)in)[2 * i];
        float4 hi = ((const float4*)in)[2 * i + 1];
        float4 o0, o1;
        o0.x = rna_tf32(lo.x); o0.y = rna_tf32(hi.x);
        o0.z = rna_tf32(lo.y); o0.w = rna_tf32(hi.y);
        o1.x = rna_tf32(lo.z); o1.y = rna_tf32(hi.z);
        o1.z = rna_tf32(lo.w); o1.w = rna_tf32(hi.w);
        ((float4*)out)[2 * i]     = o0;
        ((float4*)out)[2 * i + 1] = o1;
    }
}

#define W1_BLKS  (392 * 32)
#define W2_BLKS  (32 * 32)
__global__ void prep_w12(const float* __restrict__ w1, const float* __restrict__ w2,
                         float* __restrict__ W1t, float* __restrict__ W2t) {
    __shared__ float tsm[32][33];
    int b = blockIdx.x;
    int x = threadIdx.x, y = threadIdx.y;
    int xp = x - (x & 7) + POS(x & 7);
    if (b < W1_BLKS) {
        int kblk = b % 392, nblk = b / 392;
        int k0 = kblk * 32, n0 = nblk * 32;
#pragma unroll
        for (int yy = y; yy < 32; yy += 8)
            tsm[yy][x] = w1[(size_t)(k0 + yy) * HID + n0 + x];
        __syncthreads();
#pragma unroll
        for (int yy = y; yy < 32; yy += 8)
            W1t[(size_t)(n0 + yy) * K1 + k0 + xp] = rna_tf32(tsm[x][yy]);
    } else {
        int b2 = b - W1_BLKS;
        int kblk = b2 % 32, nblk = b2 / 32;
        int k0 = kblk * 32, n0 = nblk * 32;
#pragma unroll
        for (int yy = y; yy < 32; yy += 8)
            tsm[yy][x] = w2[(size_t)(k0 + yy) * HID + n0 + x];
        __syncthreads();
#pragma unroll
        for (int yy = y; yy < 32; yy += 8)
            W2t[(size_t)(n0 + yy) * HID + k0 + xp] = rna_tf32(tsm[x][yy]);
    }
}

__global__ void prep_heads(const float* __restrict__ wl, const float* __restrict__ wd,
                           float* __restrict__ Wht,
                           const float* __restrict__ bl, const float* __restrict__ bd,
                           float* __restrict__ bh) {
    if (blockIdx.x == 0 && threadIdx.y == 0) {
        for (int i = threadIdx.x; i < NHPAD; i += 32)
            bh[i] = (i < NCLS) ? bl[i] : (i < NHEAD ? bd[i - NCLS] : 0.f);
    }
    __shared__ float tsm[32][33];
    int kblk = blockIdx.x % 32, nblk = blockIdx.x / 32;
    int k0 = kblk * 32, n0 = nblk * 32;
    int x = threadIdx.x, y = threadIdx.y;
    int xp = x - (x & 7) + POS(x & 7);
#pragma unroll
    for (int yy = y; yy < 32; yy += 8) {
        int k = k0 + yy, n = n0 + x;
        float v = 0.f;
        if (n < NHEAD)
            v = (n < NCLS) ? wl[(size_t)k * NCLS + n]
                           : wd[(size_t)k * NDEL + (n - NCLS)];
        tsm[yy][x] = v;
    }
    __syncthreads();
#pragma unroll
    for (int yy = y; yy < 32; yy += 8) {
        int n = n0 + yy;
        if (n < NHEAD)
            Wht[(size_t)n * HID + k0 + xp] = rna_tf32(tsm[x][yy]);
    }
}

// ---------------------------------------------------------------------------
// BN / epilogue
// ---------------------------------------------------------------------------
__global__ void bn_stats_kernel(const float* __restrict__ x,
                                const float* __restrict__ gamma,
                                const float* __restrict__ beta,
                                float* __restrict__ scale, float* __restrict__ shift,
                                int M, int N) {
    int col = blockIdx.x * 32 + threadIdx.x;
    float s = 0.f, sq = 0.f;
    for (int r = threadIdx.y; r < M; r += blockDim.y) {
        float v = x[(size_t)r * N + col];
        s += v; sq += v * v;
    }
    __shared__ float ss[8][32], sg[8][32];
    ss[threadIdx.y][threadIdx.x] = s;
    sg[threadIdx.y][threadIdx.x] = sq;
    __syncthreads();
    if (threadIdx.y == 0) {
#pragma unroll
        for (int i = 1; i < 8; i++) { s += ss[i][threadIdx.x]; sq += sg[i][threadIdx.x]; }
        float mean = s / (float)M;
        float var  = sq / (float)M - mean * mean;
        float sc   = gamma[col] * rsqrtf(var + BN_EPS);
        scale[col] = sc;
        shift[col] = beta[col] - mean * sc;
    }
}

// vectorized: 8 cols per thread, rna+permute into out
__global__ void bn_relu_rna_permute8(const float* __restrict__ x, float* __restrict__ out,
                                     const float* __restrict__ scale,
                                     const float* __restrict__ shift, int n8, int N) {
    int i = blockIdx.x * blockDim.x + threadIdx.x;
    if (i < n8) {
        int base = i * 8;
        int c0 = base & (N - 1);
        float4 lo = ((const float4*)x)[2 * i];
        float4 hi = ((const float4*)x)[2 * i + 1];
        float4 sl = ((const float4*)scale)[c0 / 4];
        float4 sh = ((const float4*)scale)[c0 / 4 + 1];
        float4 fl = ((const float4*)shift)[c0 / 4];
        float4 fh = ((const float4*)shift)[c0 / 4 + 1];
        float v0 = rna_tf32(fmaxf(0.f, fmaf(lo.x, sl.x, fl.x)));
        float v1 = rna_tf32(fmaxf(0.f, fmaf(lo.y, sl.y, fl.y)));
        float v2 = rna_tf32(fmaxf(0.f, fmaf(lo.z, sl.z, fl.z)));
        float v3 = rna_tf32(fmaxf(0.f, fmaf(lo.w, sl.w, fl.w)));
        float v4 = rna_tf32(fmaxf(0.f, fmaf(hi.x, sh.x, fh.x)));
        float v5 = rna_tf32(fmaxf(0.f, fmaf(hi.y, sh.y, fh.y)));
        float v6 = rna_tf32(fmaxf(0.f, fmaf(hi.z, sh.z, fh.z)));
        float v7 = rna_tf32(fmaxf(0.f, fmaf(hi.w, sh.w, fh.w)));
        float4 o0, o1;
        o0.x = v0; o0.y = v4; o0.z = v1; o0.w = v5;
        o1.x = v2; o1.y = v6; o1.z = v3; o1.w = v7;
        ((float4*)out)[2 * i]     = o0;
        ((float4*)out)[2 * i + 1] = o1;
    }
}

__global__ void softmax_kernel(const float* __restrict__ logits,
                               float* __restrict__ probs, int M, int N) {
    int row  = blockIdx.x * (blockDim.x / 32) + threadIdx.x / 32;
    int lane = threadIdx.x & 31;
    if (row >= M) return;
    const float* lr = logits + (size_t)row * N;
    float v[3], mx = -1e30f;
#pragma unroll
    for (int j = 0; j < 3; j++) {
        int c = lane + j * 32;
        v[j] = (c < N) ? lr[c] : -1e30f;
        mx = fmaxf(mx, v[j]);
    }
#pragma unroll
    for (int o = 16; o; o >>= 1) mx = fmaxf(mx, __shfl_xor_sync(0xFFFFFFFFu, mx, o));
    float s = 0.f;
#pragma unroll
    for (int j = 0; j < 3; j++) {
        int c = lane + j * 32;
        v[j] = (c < N) ? expf(v[j] - mx) : 0.f;
        s += v[j];
    }
#pragma unroll
    for (int o = 16; o; o >>= 1) s += __shfl_xor_sync(0xFFFFFFFFu, s, o);
    float inv = 1.0f / s;
#pragma unroll
    for (int j = 0; j < 3; j++) {
        int c = lane + j * 32;
        if (c < N) probs[(size_t)row * N + c] = v[j] * inv;
    }
}

// ---------------------------------------------------------------------------
typedef CUresult (*EncodeTiledFn)(CUtensorMap*, CUtensorMapDataType, cuuint32_t,
                                  void*, const cuuint64_t*, const cuuint64_t*,
                                  const cuuint32_t*, const cuuint32_t*,
                                  CUtensorMapInterleave, CUtensorMapSwizzle,
                                  CUtensorMapL2promotion, CUtensorMapFloatOOBfill);

static void make_map2d(EncodeTiledFn enc, CUtensorMap* m, void* ptr,
                       uint64_t kdim, uint64_t rows) {
    cuuint64_t dims[2]    = {kdim, rows};
    cuuint64_t strides[1] = {kdim * 4};
    cuuint32_t box[2]     = {LDT, 128};
    cuuint32_t estr[2]    = {1, 1};
    enc(m, CU_TENSOR_MAP_DATA_TYPE_FLOAT32, 2, ptr, dims, strides, box, estr,
        CU_TENSOR_MAP_INTERLEAVE_NONE, CU_TENSOR_MAP_SWIZZLE_NONE,
        CU_TENSOR_MAP_L2_PROMOTION_L2_128B, CU_TENSOR_MAP_FLOAT_OOB_FILL_NONE);
}

extern "C" void kernel_launch(void* const* d_in, const int* in_sizes, int n_in,
                              void* d_out, int out_size) {
    const float* pooled   = (const float*)d_in[0];
    const float* w1       = (const float*)d_in[1];
    const float* b1       = (const float*)d_in[2];
    const float* gamma1   = (const float*)d_in[3];
    const float* beta1    = (const float*)d_in[4];
    const float* w2       = (const float*)d_in[5];
    const float* b2       = (const float*)d_in[6];
    const float* gamma2   = (const float*)d_in[7];
    const float* beta2    = (const float*)d_in[8];
    const float* w_logits = (const float*)d_in[9];
    const float* b_logits = (const float*)d_in[10];
    const float* w_delta  = (const float*)d_in[11];
    const float* b_delta  = (const float*)d_in[12];

    float* out        = (float*)d_out;
    float* out_logits = out;
    float* out_probs  = out + N_ROI * NCLS;
    float* out_deltas = out + 2 * N_ROI * NCLS;

    float *Ap, *W1t, *W2t, *Wht, *bh, *x1, *x1p, *x2, *x2p, *scale, *shift;
    cudaGetSymbolAddress((void**)&Ap,    g_Ap);
    cudaGetSymbolAddress((void**)&W1t,   g_W1t);
    cudaGetSymbolAddress((void**)&W2t,   g_W2t);
    cudaGetSymbolAddress((void**)&Wht,   g_Wht);
    cudaGetSymbolAddress((void**)&bh,    g_bh);
    cudaGetSymbolAddress((void**)&x1,    g_x1);
    cudaGetSymbolAddress((void**)&x1p,   g_x1p);
    cudaGetSymbolAddress((void**)&x2,    g_x2);
    cudaGetSymbolAddress((void**)&x2p,   g_x2p);
    cudaGetSymbolAddress((void**)&scale, g_scale);
    cudaGetSymbolAddress((void**)&shift, g_shift);

    EncodeTiledFn enc = nullptr;
#if CUDART_VERSION >= 12000
    cudaDriverEntryPointQueryResult qr;
    cudaGetDriverEntryPoint("cuTensorMapEncodeTiled", (void**)&enc,
                            cudaEnableDefault, &qr);
#else
    cudaGetDriverEntryPoint("cuTensorMapEncodeTiled", (void**)&enc, cudaEnableDefault);
#endif

    CUtensorMap mA1, mB1, mA2, mB2, mA3, mB3;
    make_map2d(enc, &mA1, Ap,  K1,  N_ROI);
    make_map2d(enc, &mB1, W1t, K1,  HID);
    make_map2d(enc, &mA2, x1p, HID, N_ROI);
    make_map2d(enc, &mB2, W2t, HID, HID);
    make_map2d(enc, &mA3, x2p, HID, N_ROI);
    make_map2d(enc, &mB3, Wht, HID, NHEAD);

    cudaFuncSetAttribute(gemm_tf32_tma, cudaFuncAttributeMaxDynamicSharedMemorySize, SMEM_TOT);

    // prep: 3 launches so GEMM1 is launch #4 (the one ncu profiles)
    int n8A = N_ROI * K1 / 8;
    cvt_rna_permute8<<<(n8A + 255) / 256, 256>>>(pooled, Ap, n8A);                   // 1
    prep_w12<<<W1_BLKS + W2_BLKS, dim3(32, 8)>>>(w1, w2, W1t, W2t);                  // 2
    prep_heads<<<32 * 13, dim3(32, 8)>>>(w_logits, w_delta, Wht,
                                         b_logits, b_delta, bh);                     // 3

    const int n8x = N_ROI * HID / 8;
    dim3 bn_block(32, 8);
    dim3 g1(HID / TN, (N_ROI + TM - 1) / TM);    // (8, 16)

    gemm_tf32_tma<<<g1, NTHREADS, SMEM_TOT>>>(mA1, mB1, b1, x1, nullptr, nullptr,
                                              N_ROI, K1, HID);                       // 4 (profiled)
    bn_stats_kernel<<<HID / 32, bn_block>>>(x1, gamma1, beta1, scale, shift, N_ROI, HID);
    bn_relu_rna_permute8<<<(n8x + 255) / 256, 256>>>(x1, x1p, scale, shift, n8x, HID);

    gemm_tf32_tma<<<g1, NTHREADS, SMEM_TOT>>>(mA2, mB2, b2, x2, nullptr, nullptr,
                                              N_ROI, HID, HID);
    bn_stats_kernel<<<HID / 32, bn_block>>>(x2, gamma2, beta2, scale, shift, N_ROI, HID);
    bn_relu_rna_permute8<<<(n8x + 255) / 256, 256>>>(x2, x2p, scale, shift, n8x, HID);

    dim3 gh(NHPAD / TN, (N_ROI + TM - 1) / TM);  // (4, 16)
    gemm_tf32_tma<<<gh, NTHREADS, SMEM_TOT>>>(mA3, mB3, bh, nullptr,
                                              out_logits, out_deltas, N_ROI, HID, NHPAD);
    softmax_kernel<<<(N_ROI + 7) / 8, 256>>>(out_logits, out_probs, N_ROI, NCLS);
}

// round 14
// speedup vs baseline: 1.1044x; 1.1044x over previous
#include <cuda_runtime.h>
#include <cuda.h>
#include <cstdint>

// ---------------------------------------------------------------------------
// BBoxHead via manual tf32 mma.sync GEMMs, TMA-fed, warp-specialized.
// CTA 128x128, 8 consumer warps (32x64) + 1 TMA producer, 4-stage pipeline.
// Mainloop = R9 proven form: batched fragment loads, then MMA burst.
// Operands k-permuted within k8 groups ([0,4,1,5,2,6,3,7]) -> ld.shared.v2.
// Heads GEMM writes logits/deltas directly (scatter fused).
// ---------------------------------------------------------------------------

#define N_ROI  2000
#define K1     12544
#define HID    1024
#define NCLS   81
#define NDEL   324
#define NHEAD  405
#define NHPAD  512
#define BN_EPS 1e-3f

#define POS(j) (((j) < 4) ? 2 * (j) : 2 * ((j) - 4) + 1)

__device__ float g_Ap  [N_ROI * K1];
__device__ float g_W1t [HID * K1];
__device__ float g_W2t [HID * HID];
__device__ float g_Wht [NHPAD * HID];
__device__ float g_bh  [NHPAD];
__device__ float g_x1  [2048 * HID];
__device__ float g_x1p [2048 * HID];
__device__ float g_x2  [2048 * HID];
__device__ float g_x2p [2048 * HID];
__device__ float g_scale[HID];
__device__ float g_shift[HID];

// ---------------------------------------------------------------------------
__device__ __forceinline__ uint32_t smem_u32(const void* p) {
    uint32_t a;
    asm("{ .reg .u64 t; cvta.to.shared.u64 t, %1; cvt.u32.u64 %0, t; }" : "=r"(a) : "l"(p));
    return a;
}
__device__ __forceinline__ float rna_tf32(float x) {
    uint32_t r;
    asm("cvt.rna.tf32.f32 %0, %1;" : "=r"(r) : "f"(x));
    return __uint_as_float(r);
}

#define MBAR_INIT(a, c)      asm volatile("mbarrier.init.shared.b64 [%0], %1;" :: "r"(a), "r"(c) : "memory")
#define MBAR_EXPECT_TX(a, b) asm volatile("mbarrier.arrive.expect_tx.shared.b64 _, [%0], %1;" :: "r"(a), "r"(b) : "memory")
#define MBAR_ARRIVE(a)       asm volatile("mbarrier.arrive.shared.b64 _, [%0];" :: "r"(a) : "memory")
#define MBAR_WAIT(a, ph) do {                                                     \
    uint32_t _m = (a); uint32_t _p = (ph);                                        \
    asm volatile("{\n\t.reg .pred P;\n\t"                                         \
        "WL_%=:\n\t"                                                              \
        "mbarrier.try_wait.parity.acquire.cta.shared::cta.b64 P, [%0], %1, 0x989680;\n\t" \
        "@P bra.uni WD_%=;\n\t"                                                   \
        "bra.uni WL_%=;\n\t"                                                      \
        "WD_%=:\n\t}" :: "r"(_m), "r"(_p) : "memory");                            \
} while (0)

#define TMA_LOAD_2D(saddr, mp, cx, cy, mb)                                        \
    asm volatile("cp.async.bulk.tensor.2d.shared::cta.global.tile.mbarrier::complete_tx::bytes " \
                 "[%0], [%1, {%2, %3}], [%4];"                                    \
                 :: "r"(saddr), "l"(mp), "r"(cx), "r"(cy), "r"(mb) : "memory")

#define LD2(r0, r1, addr)                                                         \
    asm volatile("ld.shared.v2.b32 {%0,%1}, [%2];" : "=r"(r0), "=r"(r1) : "r"(addr))

#define ST2(addr, v0, v1)                                                         \
    asm volatile("st.shared.v2.f32 [%0], {%1,%2};" :: "r"(addr), "f"(v0), "f"(v1) : "memory")

#define MMA(cr, A0, A1, A2, A3, B0, B1)                                           \
    asm volatile("mma.sync.aligned.m16n8k8.row.col.f32.tf32.tf32.f32 "            \
        "{%0,%1,%2,%3}, {%4,%5,%6,%7}, {%8,%9}, {%0,%1,%2,%3};"                   \
        : "+f"((cr)[0]), "+f"((cr)[1]), "+f"((cr)[2]), "+f"((cr)[3])              \
        : "r"(A0), "r"(A1), "r"(A2), "r"(A3), "r"(B0), "r"(B1))

// ---------------------------------------------------------------------------
#define LDT      40
#define TM       128
#define TN       128
#define TILE_A   (TM * LDT * 4)                   // 20480
#define STAGE_B  (2 * TILE_A)                     // 40960
#define NSTAGE   4
#define SM_TILE0 1024
#define SMEM_TOT (SM_TILE0 + NSTAGE * STAGE_B)    // 164864
#define TXBYTES  STAGE_B
#define LDE      132
#define NTHREADS 288

__global__ __launch_bounds__(NTHREADS)
void gemm_tf32_tma(const __grid_constant__ CUtensorMap mapA,
                   const __grid_constant__ CUtensorMap mapB,
                   const float* __restrict__ bias, float* __restrict__ C,
                   float* __restrict__ hd_logits, float* __restrict__ hd_deltas,
                   int M, int K, int ldC) {
    extern __shared__ float smem_f[];
    const uint32_t sb = smem_u32(smem_f);
    const int tid  = threadIdx.x;
    const int wid  = tid >> 5;
    const int lane = tid & 31;
    const int row0 = blockIdx.y * TM;
    const int col0 = blockIdx.x * TN;
    const int NK = K / 32;

    if (tid == 0) {
#pragma unroll
        for (int s = 0; s < NSTAGE; s++) {
            MBAR_INIT(sb + s * 16,     1);
            MBAR_INIT(sb + s * 16 + 8, 8);
        }
    }
    __syncthreads();

    const int warp_m = wid & 3;
    const int warp_n = wid >> 2;
    const int g = lane >> 2;
    const int t = lane & 3;

    float c0[8][4], c1[8][4];

    if (wid == 8) {
        if (lane == 0) {
            int s = 0, ph = 1;
            for (int i = 0; i < NK; i++) {
                MBAR_WAIT(sb + s * 16 + 8, ph);
                uint32_t st = sb + SM_TILE0 + s * STAGE_B;
                MBAR_EXPECT_TX(sb + s * 16, TXBYTES);
                TMA_LOAD_2D(st,          &mapA, i * 32, row0, sb + s * 16);
                TMA_LOAD_2D(st + TILE_A, &mapB, i * 32, col0, sb + s * 16);
                if (++s == NSTAGE) { s = 0; ph ^= 1; }
            }
        }
    } else {
#pragma unroll
        for (int nj = 0; nj < 8; nj++)
#pragma unroll
            for (int r = 0; r < 4; r++) { c0[nj][r] = 0.f; c1[nj][r] = 0.f; }

        const uint32_t aLane = ((warp_m * 32 + g) * LDT + 2 * t) * 4;
        const uint32_t bLane = ((warp_n * 64 + g) * LDT + 2 * t) * 4;

        int s = 0, ph = 0;
        for (int i = 0; i < NK; i++) {
            MBAR_WAIT(sb + s * 16, ph);
            const uint32_t sA = sb + SM_TILE0 + s * STAGE_B + aLane;
            const uint32_t sB = sb + SM_TILE0 + s * STAGE_B + TILE_A + bLane;

#pragma unroll
            for (int ks = 0; ks < 4; ks++) {
                const uint32_t ko = ks * 32;           // 8 floats
                uint32_t A0, A1, A2, A3, A4, A5, A6, A7;
                LD2(A0, A2, sA + ko);
                LD2(A1, A3, sA + 8  * LDT * 4 + ko);
                LD2(A4, A6, sA + 16 * LDT * 4 + ko);
                LD2(A5, A7, sA + 24 * LDT * 4 + ko);
                uint32_t B0[8], B1[8];
#pragma unroll
                for (int nj = 0; nj < 8; nj++)
                    LD2(B0[nj], B1[nj], sB + nj * 8 * LDT * 4 + ko);
#pragma unroll
                for (int nj = 0; nj < 8; nj++)
                    MMA(c0[nj], A0, A1, A2, A3, B0[nj], B1[nj]);
#pragma unroll
                for (int nj = 0; nj < 8; nj++)
                    MMA(c1[nj], A4, A5, A6, A7, B0[nj], B1[nj]);
            }

            if (lane == 0) MBAR_ARRIVE(sb + s * 16 + 8);
            if (++s == NSTAGE) { s = 0; ph ^= 1; }
        }
    }
    __syncthreads();

    if (wid != 8) {
        const uint32_t eb = sb;
#pragma unroll
        for (int nj = 0; nj < 8; nj++) {
            uint32_t colb = (warp_n * 64 + nj * 8 + 2 * t) * 4;
            uint32_t r0 = (warp_m * 32 + g) * LDE * 4;
            ST2(eb + r0 + colb,                c0[nj][0], c0[nj][1]);
            ST2(eb + r0 + 8  * LDE * 4 + colb, c0[nj][2], c0[nj][3]);
            ST2(eb + r0 + 16 * LDE * 4 + colb, c1[nj][0], c1[nj][1]);
            ST2(eb + r0 + 24 * LDE * 4 + colb, c1[nj][2], c1[nj][3]);
        }
    }
    __syncthreads();

    const float* esm = smem_f;
    if (hd_deltas == nullptr) {
#pragma unroll 2
        for (int e = tid; e < TM * 32; e += NTHREADS) {
            int r  = e >> 5;
            int c4 = (e & 31) * 4;
            int gr = row0 + r;
            if (gr < M) {
                const float* sp = esm + r * LDE + c4;
                float4 v;
                v.x = sp[0] + bias[col0 + c4 + 0];
                v.y = sp[1] + bias[col0 + c4 + 1];
                v.z = sp[2] + bias[col0 + c4 + 2];
                v.w = sp[3] + bias[col0 + c4 + 3];
                *(float4*)&C[(size_t)gr * ldC + col0 + c4] = v;
            }
        }
    } else {
        for (int e = tid; e < TM * TN; e += NTHREADS) {
            int r  = e >> 7;
            int c  = e & 127;
            int gr = row0 + r;
            int gc = col0 + c;
            if (gr < M && gc < NHEAD) {
                float v = esm[r * LDE + c] + bias[gc];
                if (gc < NCLS) hd_logits[(size_t)gr * NCLS + gc] = v;
                else           hd_deltas[(size_t)gr * NDEL + (gc - NCLS)] = v;
            }
        }
    }
}

// ---------------------------------------------------------------------------
// Prep kernels
// ---------------------------------------------------------------------------
__global__ void cvt_rna_permute8(const float* __restrict__ in, float* __restrict__ out,
                                 int n8) {
    int i = blockIdx.x * blockDim.x + threadIdx.x;
    if (i < n8) {
        float4 lo = ((const float4*)in)[2 * i];
        float4 hi = ((const float4*)in)[2 * i + 1];
        float4 o0, o1;
        o0.x = rna_tf32(lo.x); o0.y = rna_tf32(hi.x);
        o0.z = rna_tf32(lo.y); o0.w = rna_tf32(hi.y);
        o1.x = rna_tf32(lo.z); o1.y = rna_tf32(hi.z);
        o1.z = rna_tf32(lo.w); o1.w = rna_tf32(hi.w);
        ((float4*)out)[2 * i]     = o0;
        ((float4*)out)[2 * i + 1] = o1;
    }
}

#define W1_BLKS  (392 * 32)
#define W2_BLKS  (32 * 32)
__global__ void prep_w12(const float* __restrict__ w1, const float* __restrict__ w2,
                         float* __restrict__ W1t, float* __restrict__ W2t) {
    __shared__ float tsm[32][33];
    int b = blockIdx.x;
    int x = threadIdx.x, y = threadIdx.y;
    int xp = x - (x & 7) + POS(x & 7);
    if (b < W1_BLKS) {
        int kblk = b % 392, nblk = b / 392;
        int k0 = kblk * 32, n0 = nblk * 32;
#pragma unroll
        for (int yy = y; yy < 32; yy += 8)
            tsm[yy][x] = w1[(size_t)(k0 + yy) * HID + n0 + x];
        __syncthreads();
#pragma unroll
        for (int yy = y; yy < 32; yy += 8)
            W1t[(size_t)(n0 + yy) * K1 + k0 + xp] = rna_tf32(tsm[x][yy]);
    } else {
        int b2 = b - W1_BLKS;
        int kblk = b2 % 32, nblk = b2 / 32;
        int k0 = kblk * 32, n0 = nblk * 32;
#pragma unroll
        for (int yy = y; yy < 32; yy += 8)
            tsm[yy][x] = w2[(size_t)(k0 + yy) * HID + n0 + x];
        __syncthreads();
#pragma unroll
        for (int yy = y; yy < 32; yy += 8)
            W2t[(size_t)(n0 + yy) * HID + k0 + xp] = rna_tf32(tsm[x][yy]);
    }
}

__global__ void prep_heads(const float* __restrict__ wl, const float* __restrict__ wd,
                           float* __restrict__ Wht,
                           const float* __restrict__ bl, const float* __restrict__ bd,
                           float* __restrict__ bh) {
    if (blockIdx.x == 0 && threadIdx.y == 0) {
        for (int i = threadIdx.x; i < NHPAD; i += 32)
            bh[i] = (i < NCLS) ? bl[i] : (i < NHEAD ? bd[i - NCLS] : 0.f);
    }
    __shared__ float tsm[32][33];
    int kblk = blockIdx.x % 32, nblk = blockIdx.x / 32;
    int k0 = kblk * 32, n0 = nblk * 32;
    int x = threadIdx.x, y = threadIdx.y;
    int xp = x - (x & 7) + POS(x & 7);
#pragma unroll
    for (int yy = y; yy < 32; yy += 8) {
        int k = k0 + yy, n = n0 + x;
        float v = 0.f;
        if (n < NHEAD)
            v = (n < NCLS) ? wl[(size_t)k * NCLS + n]
                           : wd[(size_t)k * NDEL + (n - NCLS)];
        tsm[yy][x] = v;
    }
    __syncthreads();
#pragma unroll
    for (int yy = y; yy < 32; yy += 8) {
        int n = n0 + yy;
        if (n < NHEAD)
            Wht[(size_t)n * HID + k0 + xp] = rna_tf32(tsm[x][yy]);
    }
}

// ---------------------------------------------------------------------------
// BN / epilogue
// ---------------------------------------------------------------------------
__global__ void bn_stats_kernel(const float* __restrict__ x,
                                const float* __restrict__ gamma,
                                const float* __restrict__ beta,
                                float* __restrict__ scale, float* __restrict__ shift,
                                int M, int N) {
    int col = blockIdx.x * 32 + threadIdx.x;
    float s = 0.f, sq = 0.f;
    for (int r = threadIdx.y; r < M; r += blockDim.y) {
        float v = x[(size_t)r * N + col];
        s += v; sq += v * v;
    }
    __shared__ float ss[8][32], sg[8][32];
    ss[threadIdx.y][threadIdx.x] = s;
    sg[threadIdx.y][threadIdx.x] = sq;
    __syncthreads();
    if (threadIdx.y == 0) {
#pragma unroll
        for (int i = 1; i < 8; i++) { s += ss[i][threadIdx.x]; sq += sg[i][threadIdx.x]; }
        float mean = s / (float)M;
        float var  = sq / (float)M - mean * mean;
        float sc   = gamma[col] * rsqrtf(var + BN_EPS);
        scale[col] = sc;
        shift[col] = beta[col] - mean * sc;
    }
}

__global__ void bn_relu_rna_permute8(const float* __restrict__ x, float* __restrict__ out,
                                     const float* __restrict__ scale,
                                     const float* __restrict__ shift, int n8, int N) {
    int i = blockIdx.x * blockDim.x + threadIdx.x;
    if (i < n8) {
        int base = i * 8;
        int c0 = base & (N - 1);
        float4 lo = ((const float4*)x)[2 * i];
        float4 hi = ((const float4*)x)[2 * i + 1];
        float4 sl = ((const float4*)scale)[c0 / 4];
        float4 sh = ((const float4*)scale)[c0 / 4 + 1];
        float4 fl = ((const float4*)shift)[c0 / 4];
        float4 fh = ((const float4*)shift)[c0 / 4 + 1];
        float v0 = rna_tf32(fmaxf(0.f, fmaf(lo.x, sl.x, fl.x)));
        float v1 = rna_tf32(fmaxf(0.f, fmaf(lo.y, sl.y, fl.y)));
        float v2 = rna_tf32(fmaxf(0.f, fmaf(lo.z, sl.z, fl.z)));
        float v3 = rna_tf32(fmaxf(0.f, fmaf(lo.w, sl.w, fl.w)));
        float v4 = rna_tf32(fmaxf(0.f, fmaf(hi.x, sh.x, fh.x)));
        float v5 = rna_tf32(fmaxf(0.f, fmaf(hi.y, sh.y, fh.y)));
        float v6 = rna_tf32(fmaxf(0.f, fmaf(hi.z, sh.z, fh.z)));
        float v7 = rna_tf32(fmaxf(0.f, fmaf(hi.w, sh.w, fh.w)));
        float4 o0, o1;
        o0.x = v0; o0.y = v4; o0.z = v1; o0.w = v5;
        o1.x = v2; o1.y = v6; o1.z = v3; o1.w = v7;
        ((float4*)out)[2 * i]     = o0;
        ((float4*)out)[2 * i + 1] = o1;
    }
}

__global__ void softmax_kernel(const float* __restrict__ logits,
                               float* __restrict__ probs, int M, int N) {
    int row  = blockIdx.x * (blockDim.x / 32) + threadIdx.x / 32;
    int lane = threadIdx.x & 31;
    if (row >= M) return;
    const float* lr = logits + (size_t)row * N;
    float v[3], mx = -1e30f;
#pragma unroll
    for (int j = 0; j < 3; j++) {
        int c = lane + j * 32;
        v[j] = (c < N) ? lr[c] : -1e30f;
        mx = fmaxf(mx, v[j]);
    }
#pragma unroll
    for (int o = 16; o; o >>= 1) mx = fmaxf(mx, __shfl_xor_sync(0xFFFFFFFFu, mx, o));
    float s = 0.f;
#pragma unroll
    for (int j = 0; j < 3; j++) {
        int c = lane + j * 32;
        v[j] = (c < N) ? expf(v[j] - mx) : 0.f;
        s += v[j];
    }
#pragma unroll
    for (int o = 16; o; o >>= 1) s += __shfl_xor_sync(0xFFFFFFFFu, s, o);
    float inv = 1.0f / s;
#pragma unroll
    for (int j = 0; j < 3; j++) {
        int c = lane + j * 32;
        if (c < N) probs[(size_t)row * N + c] = v[j] * inv;
    }
}

// ---------------------------------------------------------------------------
typedef CUresult (*EncodeTiledFn)(CUtensorMap*, CUtensorMapDataType, cuuint32_t,
                                  void*, const cuuint64_t*, const cuuint64_t*,
                                  const cuuint32_t*, const cuuint32_t*,
                                  CUtensorMapInterleave, CUtensorMapSwizzle,
                                  CUtensorMapL2promotion, CUtensorMapFloatOOBfill);

static void make_map2d(EncodeTiledFn enc, CUtensorMap* m, void* ptr,
                       uint64_t kdim, uint64_t rows) {
    cuuint64_t dims[2]    = {kdim, rows};
    cuuint64_t strides[1] = {kdim * 4};
    cuuint32_t box[2]     = {LDT, 128};
    cuuint32_t estr[2]    = {1, 1};
    enc(m, CU_TENSOR_MAP_DATA_TYPE_FLOAT32, 2, ptr, dims, strides, box, estr,
        CU_TENSOR_MAP_INTERLEAVE_NONE, CU_TENSOR_MAP_SWIZZLE_NONE,
        CU_TENSOR_MAP_L2_PROMOTION_L2_128B, CU_TENSOR_MAP_FLOAT_OOB_FILL_NONE);
}

extern "C" void kernel_launch(void* const* d_in, const int* in_sizes, int n_in,
                              void* d_out, int out_size) {
    const float* pooled   = (const float*)d_in[0];
    const float* w1       = (const float*)d_in[1];
    const float* b1       = (const float*)d_in[2];
    const float* gamma1   = (const float*)d_in[3];
    const float* beta1    = (const float*)d_in[4];
    const float* w2       = (const float*)d_in[5];
    const float* b2       = (const float*)d_in[6];
    const float* gamma2   = (const float*)d_in[7];
    const float* beta2    = (const float*)d_in[8];
    const float* w_logits = (const float*)d_in[9];
    const float* b_logits = (const float*)d_in[10];
    const float* w_delta  = (const float*)d_in[11];
    const float* b_delta  = (const float*)d_in[12];

    float* out        = (float*)d_out;
    float* out_logits = out;
    float* out_probs  = out + N_ROI * NCLS;
    float* out_deltas = out + 2 * N_ROI * NCLS;

    float *Ap, *W1t, *W2t, *Wht, *bh, *x1, *x1p, *x2, *x2p, *scale, *shift;
    cudaGetSymbolAddress((void**)&Ap,    g_Ap);
    cudaGetSymbolAddress((void**)&W1t,   g_W1t);
    cudaGetSymbolAddress((void**)&W2t,   g_W2t);
    cudaGetSymbolAddress((void**)&Wht,   g_Wht);
    cudaGetSymbolAddress((void**)&bh,    g_bh);
    cudaGetSymbolAddress((void**)&x1,    g_x1);
    cudaGetSymbolAddress((void**)&x1p,   g_x1p);
    cudaGetSymbolAddress((void**)&x2,    g_x2);
    cudaGetSymbolAddress((void**)&x2p,   g_x2p);
    cudaGetSymbolAddress((void**)&scale, g_scale);
    cudaGetSymbolAddress((void**)&shift, g_shift);

    EncodeTiledFn enc = nullptr;
#if CUDART_VERSION >= 12000
    cudaDriverEntryPointQueryResult qr;
    cudaGetDriverEntryPoint("cuTensorMapEncodeTiled", (void**)&enc,
                            cudaEnableDefault, &qr);
#else
    cudaGetDriverEntryPoint("cuTensorMapEncodeTiled", (void**)&enc, cudaEnableDefault);
#endif

    CUtensorMap mA1, mB1, mA2, mB2, mA3, mB3;
    make_map2d(enc, &mA1, Ap,  K1,  N_ROI);
    make_map2d(enc, &mB1, W1t, K1,  HID);
    make_map2d(enc, &mA2, x1p, HID, N_ROI);
    make_map2d(enc, &mB2, W2t, HID, HID);
    make_map2d(enc, &mA3, x2p, HID, N_ROI);
    make_map2d(enc, &mB3, Wht, HID, NHEAD);

    cudaFuncSetAttribute(gemm_tf32_tma, cudaFuncAttributeMaxDynamicSharedMemorySize, SMEM_TOT);

    // prep: 3 launches so GEMM1 is launch #4 (the one ncu profiles)
    int n8A = N_ROI * K1 / 8;
    cvt_rna_permute8<<<(n8A + 255) / 256, 256>>>(pooled, Ap, n8A);                   // 1
    prep_w12<<<W1_BLKS + W2_BLKS, dim3(32, 8)>>>(w1, w2, W1t, W2t);                  // 2
    prep_heads<<<32 * 13, dim3(32, 8)>>>(w_logits, w_delta, Wht,
                                         b_logits, b_delta, bh);                     // 3

    const int n8x = N_ROI * HID / 8;
    dim3 bn_block(32, 8);
    dim3 g1(HID / TN, (N_ROI + TM - 1) / TM);    // (8, 16)

    gemm_tf32_tma<<<g1, NTHREADS, SMEM_TOT>>>(mA1, mB1, b1, x1, nullptr, nullptr,
                                              N_ROI, K1, HID);                       // 4 (profiled)
    bn_stats_kernel<<<HID / 32, bn_block>>>(x1, gamma1, beta1, scale, shift, N_ROI, HID);
    bn_relu_rna_permute8<<<(n8x + 255) / 256, 256>>>(x1, x1p, scale, shift, n8x, HID);

    gemm_tf32_tma<<<g1, NTHREADS, SMEM_TOT>>>(mA2, mB2, b2, x2, nullptr, nullptr,
                                              N_ROI, HID, HID);
    bn_stats_kernel<<<HID / 32, bn_block>>>(x2, gamma2, beta2, scale, shift, N_ROI, HID);
    bn_relu_rna_permute8<<<(n8x + 255) / 256, 256>>>(x2, x2p, scale, shift, n8x, HID);

    dim3 gh(NHPAD / TN, (N_ROI + TM - 1) / TM);  // (4, 16)
    gemm_tf32_tma<<<gh, NTHREADS, SMEM_TOT>>>(mA3, mB3, bh, nullptr,
                                              out_logits, out_deltas, N_ROI, HID, NHPAD);
    softmax_kernel<<<(N_ROI + 7) / 8, 256>>>(out_logits, out_probs, N_ROI, NCLS);
}

// round 15
// speedup vs baseline: 1.1988x; 1.0855x over previous
#include <cuda_runtime.h>
#include <cuda.h>
#include <cstdint>

// ---------------------------------------------------------------------------
// BBoxHead via manual tf32 mma.sync GEMMs, TMA-fed, warp-specialized.
// CTA 128x128, 8 consumer warps (32x64) + 1 TMA producer, 4-stage pipeline.
// Mainloop: batched fragment loads with IMMEDIATE-offset LDS (no address
// IADDs), then MMA burst. Operands k-permuted ([0,4,1,5,2,6,3,7]) -> LDS.64.
// Heads GEMM writes logits/deltas directly (scatter fused).
// ---------------------------------------------------------------------------

#define N_ROI  2000
#define K1     12544
#define HID    1024
#define NCLS   81
#define NDEL   324
#define NHEAD  405
#define NHPAD  512
#define BN_EPS 1e-3f

#define POS(j) (((j) < 4) ? 2 * (j) : 2 * ((j) - 4) + 1)

__device__ float g_Ap  [N_ROI * K1];
__device__ float g_W1t [HID * K1];
__device__ float g_W2t [HID * HID];
__device__ float g_Wht [NHPAD * HID];
__device__ float g_bh  [NHPAD];
__device__ float g_x1  [2048 * HID];
__device__ float g_x1p [2048 * HID];
__device__ float g_x2  [2048 * HID];
__device__ float g_x2p [2048 * HID];
__device__ float g_scale[HID];
__device__ float g_shift[HID];

// ---------------------------------------------------------------------------
__device__ __forceinline__ uint32_t smem_u32(const void* p) {
    uint32_t a;
    asm("{ .reg .u64 t; cvta.to.shared.u64 t, %1; cvt.u32.u64 %0, t; }" : "=r"(a) : "l"(p));
    return a;
}
__device__ __forceinline__ float rna_tf32(float x) {
    uint32_t r;
    asm("cvt.rna.tf32.f32 %0, %1;" : "=r"(r) : "f"(x));
    return __uint_as_float(r);
}

#define MBAR_INIT(a, c)      asm volatile("mbarrier.init.shared.b64 [%0], %1;" :: "r"(a), "r"(c) : "memory")
#define MBAR_EXPECT_TX(a, b) asm volatile("mbarrier.arrive.expect_tx.shared.b64 _, [%0], %1;" :: "r"(a), "r"(b) : "memory")
#define MBAR_ARRIVE(a)       asm volatile("mbarrier.arrive.shared.b64 _, [%0];" :: "r"(a) : "memory")
#define MBAR_WAIT(a, ph) do {                                                     \
    uint32_t _m = (a); uint32_t _p = (ph);                                        \
    asm volatile("{\n\t.reg .pred P;\n\t"                                         \
        "WL_%=:\n\t"                                                              \
        "mbarrier.try_wait.parity.acquire.cta.shared::cta.b64 P, [%0], %1, 0x989680;\n\t" \
        "@P bra.uni WD_%=;\n\t"                                                   \
        "bra.uni WL_%=;\n\t"                                                      \
        "WD_%=:\n\t}" :: "r"(_m), "r"(_p) : "memory");                            \
} while (0)

#define TMA_LOAD_2D(saddr, mp, cx, cy, mb)                                        \
    asm volatile("cp.async.bulk.tensor.2d.shared::cta.global.tile.mbarrier::complete_tx::bytes " \
                 "[%0], [%1, {%2, %3}], [%4];"                                    \
                 :: "r"(saddr), "l"(mp), "r"(cx), "r"(cy), "r"(mb) : "memory")

// immediate-offset LDS.64: base reg + compile-time constant offset
#define LD2O(r0, r1, base, off)                                                   \
    asm volatile("ld.shared.v2.b32 {%0,%1}, [%2+%3];"                             \
        : "=r"(r0), "=r"(r1) : "r"(base), "n"(off))

#define ST2(addr, v0, v1)                                                         \
    asm volatile("st.shared.v2.f32 [%0], {%1,%2};" :: "r"(addr), "f"(v0), "f"(v1) : "memory")

#define MMA(cr, A0, A1, A2, A3, B0, B1)                                           \
    asm volatile("mma.sync.aligned.m16n8k8.row.col.f32.tf32.tf32.f32 "            \
        "{%0,%1,%2,%3}, {%4,%5,%6,%7}, {%8,%9}, {%0,%1,%2,%3};"                   \
        : "+f"((cr)[0]), "+f"((cr)[1]), "+f"((cr)[2]), "+f"((cr)[3])              \
        : "r"(A0), "r"(A1), "r"(A2), "r"(A3), "r"(B0), "r"(B1))

// ---------------------------------------------------------------------------
#define LDT      40
#define TM       128
#define TN       128
#define TILE_A   (TM * LDT * 4)                   // 20480
#define STAGE_B  (2 * TILE_A)                     // 40960
#define NSTAGE   4
#define SM_TILE0 1024
#define SMEM_TOT (SM_TILE0 + NSTAGE * STAGE_B)    // 164864
#define TXBYTES  STAGE_B
#define LDE      132
#define NTHREADS 288

// one ks-step: 4 A LDS.64 + 8 B LDS.64 (all immediate offsets), then 16 MMAs
#define KS_STEP(ks)                                                               \
    do {                                                                          \
        uint32_t A0, A1, A2, A3, A4, A5, A6, A7;                                  \
        LD2O(A0, A2, sA, (ks) * 32);                                              \
        LD2O(A1, A3, sA, 8  * LDT * 4 + (ks) * 32);                               \
        LD2O(A4, A6, sA, 16 * LDT * 4 + (ks) * 32);                               \
        LD2O(A5, A7, sA, 24 * LDT * 4 + (ks) * 32);                               \
        uint32_t B0[8], B1[8];                                                    \
        LD2O(B0[0], B1[0], sB, 0 * 8 * LDT * 4 + (ks) * 32);                      \
        LD2O(B0[1], B1[1], sB, 1 * 8 * LDT * 4 + (ks) * 32);                      \
        LD2O(B0[2], B1[2], sB, 2 * 8 * LDT * 4 + (ks) * 32);                      \
        LD2O(B0[3], B1[3], sB, 3 * 8 * LDT * 4 + (ks) * 32);                      \
        LD2O(B0[4], B1[4], sB, 4 * 8 * LDT * 4 + (ks) * 32);                      \
        LD2O(B0[5], B1[5], sB, 5 * 8 * LDT * 4 + (ks) * 32);                      \
        LD2O(B0[6], B1[6], sB, 6 * 8 * LDT * 4 + (ks) * 32);                      \
        LD2O(B0[7], B1[7], sB, 7 * 8 * LDT * 4 + (ks) * 32);                      \
        MMA(c0[0], A0, A1, A2, A3, B0[0], B1[0]);                                 \
        MMA(c0[1], A0, A1, A2, A3, B0[1], B1[1]);                                 \
        MMA(c0[2], A0, A1, A2, A3, B0[2], B1[2]);                                 \
        MMA(c0[3], A0, A1, A2, A3, B0[3], B1[3]);                                 \
        MMA(c0[4], A0, A1, A2, A3, B0[4], B1[4]);                                 \
        MMA(c0[5], A0, A1, A2, A3, B0[5], B1[5]);                                 \
        MMA(c0[6], A0, A1, A2, A3, B0[6], B1[6]);                                 \
        MMA(c0[7], A0, A1, A2, A3, B0[7], B1[7]);                                 \
        MMA(c1[0], A4, A5, A6, A7, B0[0], B1[0]);                                 \
        MMA(c1[1], A4, A5, A6, A7, B0[1], B1[1]);                                 \
        MMA(c1[2], A4, A5, A6, A7, B0[2], B1[2]);                                 \
        MMA(c1[3], A4, A5, A6, A7, B0[3], B1[3]);                                 \
        MMA(c1[4], A4, A5, A6, A7, B0[4], B1[4]);                                 \
        MMA(c1[5], A4, A5, A6, A7, B0[5], B1[5]);                                 \
        MMA(c1[6], A4, A5, A6, A7, B0[6], B1[6]);                                 \
        MMA(c1[7], A4, A5, A6, A7, B0[7], B1[7]);                                 \
    } while (0)

__global__ __launch_bounds__(NTHREADS)
void gemm_tf32_tma(const __grid_constant__ CUtensorMap mapA,
                   const __grid_constant__ CUtensorMap mapB,
                   const float* __restrict__ bias, float* __restrict__ C,
                   float* __restrict__ hd_logits, float* __restrict__ hd_deltas,
                   int M, int K, int ldC) {
    extern __shared__ float smem_f[];
    const uint32_t sb = smem_u32(smem_f);
    const int tid  = threadIdx.x;
    const int wid  = tid >> 5;
    const int lane = tid & 31;
    const int row0 = blockIdx.y * TM;
    const int col0 = blockIdx.x * TN;
    const int NK = K / 32;

    if (tid == 0) {
#pragma unroll
        for (int s = 0; s < NSTAGE; s++) {
            MBAR_INIT(sb + s * 16,     1);
            MBAR_INIT(sb + s * 16 + 8, 8);
        }
    }
    __syncthreads();

    const int warp_m = wid & 3;
    const int warp_n = wid >> 2;
    const int g = lane >> 2;
    const int t = lane & 3;

    float c0[8][4], c1[8][4];

    if (wid == 8) {
        if (lane == 0) {
            int s = 0, ph = 1;
            for (int i = 0; i < NK; i++) {
                MBAR_WAIT(sb + s * 16 + 8, ph);
                uint32_t st = sb + SM_TILE0 + s * STAGE_B;
                MBAR_EXPECT_TX(sb + s * 16, TXBYTES);
                TMA_LOAD_2D(st,          &mapA, i * 32, row0, sb + s * 16);
                TMA_LOAD_2D(st + TILE_A, &mapB, i * 32, col0, sb + s * 16);
                if (++s == NSTAGE) { s = 0; ph ^= 1; }
            }
        }
    } else {
#pragma unroll
        for (int nj = 0; nj < 8; nj++)
#pragma unroll
            for (int r = 0; r < 4; r++) { c0[nj][r] = 0.f; c1[nj][r] = 0.f; }

        const uint32_t aLane = ((warp_m * 32 + g) * LDT + 2 * t) * 4;
        const uint32_t bLane = ((warp_n * 64 + g) * LDT + 2 * t) * 4;

        int s = 0, ph = 0;
        for (int i = 0; i < NK; i++) {
            MBAR_WAIT(sb + s * 16, ph);
            const uint32_t sA = sb + SM_TILE0 + s * STAGE_B + aLane;
            const uint32_t sB = sb + SM_TILE0 + s * STAGE_B + TILE_A + bLane;

            KS_STEP(0);
            KS_STEP(1);
            KS_STEP(2);
            KS_STEP(3);

            if (lane == 0) MBAR_ARRIVE(sb + s * 16 + 8);
            if (++s == NSTAGE) { s = 0; ph ^= 1; }
        }
    }
    __syncthreads();

    if (wid != 8) {
        const uint32_t eb = sb;
#pragma unroll
        for (int nj = 0; nj < 8; nj++) {
            uint32_t colb = (warp_n * 64 + nj * 8 + 2 * t) * 4;
            uint32_t r0 = (warp_m * 32 + g) * LDE * 4;
            ST2(eb + r0 + colb,                c0[nj][0], c0[nj][1]);
            ST2(eb + r0 + 8  * LDE * 4 + colb, c0[nj][2], c0[nj][3]);
            ST2(eb + r0 + 16 * LDE * 4 + colb, c1[nj][0], c1[nj][1]);
            ST2(eb + r0 + 24 * LDE * 4 + colb, c1[nj][2], c1[nj][3]);
        }
    }
    __syncthreads();

    const float* esm = smem_f;
    if (hd_deltas == nullptr) {
#pragma unroll 2
        for (int e = tid; e < TM * 32; e += NTHREADS) {
            int r  = e >> 5;
            int c4 = (e & 31) * 4;
            int gr = row0 + r;
            if (gr < M) {
                const float* sp = esm + r * LDE + c4;
                float4 v;
                v.x = sp[0] + bias[col0 + c4 + 0];
                v.y = sp[1] + bias[col0 + c4 + 1];
                v.z = sp[2] + bias[col0 + c4 + 2];
                v.w = sp[3] + bias[col0 + c4 + 3];
                *(float4*)&C[(size_t)gr * ldC + col0 + c4] = v;
            }
        }
    } else {
        for (int e = tid; e < TM * TN; e += NTHREADS) {
            int r  = e >> 7;
            int c  = e & 127;
            int gr = row0 + r;
            int gc = col0 + c;
            if (gr < M && gc < NHEAD) {
                float v = esm[r * LDE + c] + bias[gc];
                if (gc < NCLS) hd_logits[(size_t)gr * NCLS + gc] = v;
                else           hd_deltas[(size_t)gr * NDEL + (gc - NCLS)] = v;
            }
        }
    }
}

// ---------------------------------------------------------------------------
// Prep kernels
// ---------------------------------------------------------------------------
__global__ void cvt_rna_permute8(const float* __restrict__ in, float* __restrict__ out,
                                 int n8) {
    int i = blockIdx.x * blockDim.x + threadIdx.x;
    if (i < n8) {
        float4 lo = ((const float4*)in)[2 * i];
        float4 hi = ((const float4*)in)[2 * i + 1];
        float4 o0, o1;
        o0.x = rna_tf32(lo.x); o0.y = rna_tf32(hi.x);
        o0.z = rna_tf32(lo.y); o0.w = rna_tf32(hi.y);
        o1.x = rna_tf32(lo.z); o1.y = rna_tf32(hi.z);
        o1.z = rna_tf32(lo.w); o1.w = rna_tf32(hi.w);
        ((float4*)out)[2 * i]     = o0;
        ((float4*)out)[2 * i + 1] = o1;
    }
}

#define W1_BLKS  (392 * 32)
#define W2_BLKS  (32 * 32)
__global__ void prep_w12(const float* __restrict__ w1, const float* __restrict__ w2,
                         float* __restrict__ W1t, float* __restrict__ W2t) {
    __shared__ float tsm[32][33];
    int b = blockIdx.x;
    int x = threadIdx.x, y = threadIdx.y;
    int xp = x - (x & 7) + POS(x & 7);
    if (b < W1_BLKS) {
        int kblk = b % 392, nblk = b / 392;
        int k0 = kblk * 32, n0 = nblk * 32;
#pragma unroll
        for (int yy = y; yy < 32; yy += 8)
            tsm[yy][x] = w1[(size_t)(k0 + yy) * HID + n0 + x];
        __syncthreads();
#pragma unroll
        for (int yy = y; yy < 32; yy += 8)
            W1t[(size_t)(n0 + yy) * K1 + k0 + xp] = rna_tf32(tsm[x][yy]);
    } else {
        int b2 = b - W1_BLKS;
        int kblk = b2 % 32, nblk = b2 / 32;
        int k0 = kblk * 32, n0 = nblk * 32;
#pragma unroll
        for (int yy = y; yy < 32; yy += 8)
            tsm[yy][x] = w2[(size_t)(k0 + yy) * HID + n0 + x];
        __syncthreads();
#pragma unroll
        for (int yy = y; yy < 32; yy += 8)
            W2t[(size_t)(n0 + yy) * HID + k0 + xp] = rna_tf32(tsm[x][yy]);
    }
}

__global__ void prep_heads(const float* __restrict__ wl, const float* __restrict__ wd,
                           float* __restrict__ Wht,
                           const float* __restrict__ bl, const float* __restrict__ bd,
                           float* __restrict__ bh) {
    if (blockIdx.x == 0 && threadIdx.y == 0) {
        for (int i = threadIdx.x; i < NHPAD; i += 32)
            bh[i] = (i < NCLS) ? bl[i] : (i < NHEAD ? bd[i - NCLS] : 0.f);
    }
    __shared__ float tsm[32][33];
    int kblk = blockIdx.x % 32, nblk = blockIdx.x / 32;
    int k0 = kblk * 32, n0 = nblk * 32;
    int x = threadIdx.x, y = threadIdx.y;
    int xp = x - (x & 7) + POS(x & 7);
#pragma unroll
    for (int yy = y; yy < 32; yy += 8) {
        int k = k0 + yy, n = n0 + x;
        float v = 0.f;
        if (n < NHEAD)
            v = (n < NCLS) ? wl[(size_t)k * NCLS + n]
                           : wd[(size_t)k * NDEL + (n - NCLS)];
        tsm[yy][x] = v;
    }
    __syncthreads();
#pragma unroll
    for (int yy = y; yy < 32; yy += 8) {
        int n = n0 + yy;
        if (n < NHEAD)
            Wht[(size_t)n * HID + k0 + xp] = rna_tf32(tsm[x][yy]);
    }
}

// ---------------------------------------------------------------------------
// BN / epilogue
// ---------------------------------------------------------------------------
__global__ void bn_stats_kernel(const float* __restrict__ x,
                                const float* __restrict__ gamma,
                                const float* __restrict__ beta,
                                float* __restrict__ scale, float* __restrict__ shift,
                                int M, int N) {
    int col = blockIdx.x * 32 + threadIdx.x;
    float s = 0.f, sq = 0.f;
    for (int r = threadIdx.y; r < M; r += blockDim.y) {
        float v = x[(size_t)r * N + col];
        s += v; sq += v * v;
    }
    __shared__ float ss[8][32], sg[8][32];
    ss[threadIdx.y][threadIdx.x] = s;
    sg[threadIdx.y][threadIdx.x] = sq;
    __syncthreads();
    if (threadIdx.y == 0) {
#pragma unroll
        for (int i = 1; i < 8; i++) { s += ss[i][threadIdx.x]; sq += sg[i][threadIdx.x]; }
        float mean = s / (float)M;
        float var  = sq / (float)M - mean * mean;
        float sc   = gamma[col] * rsqrtf(var + BN_EPS);
        scale[col] = sc;
        shift[col] = beta[col] - mean * sc;
    }
}

__global__ void bn_relu_rna_permute8(const float* __restrict__ x, float* __restrict__ out,
                                     const float* __restrict__ scale,
                                     const float* __restrict__ shift, int n8, int N) {
    int i = blockIdx.x * blockDim.x + threadIdx.x;
    if (i < n8) {
        int base = i * 8;
        int c0 = base & (N - 1);
        float4 lo = ((const float4*)x)[2 * i];
        float4 hi = ((const float4*)x)[2 * i + 1];
        float4 sl = ((const float4*)scale)[c0 / 4];
        float4 sh = ((const float4*)scale)[c0 / 4 + 1];
        float4 fl = ((const float4*)shift)[c0 / 4];
        float4 fh = ((const float4*)shift)[c0 / 4 + 1];
        float v0 = rna_tf32(fmaxf(0.f, fmaf(lo.x, sl.x, fl.x)));
        float v1 = rna_tf32(fmaxf(0.f, fmaf(lo.y, sl.y, fl.y)));
        float v2 = rna_tf32(fmaxf(0.f, fmaf(lo.z, sl.z, fl.z)));
        float v3 = rna_tf32(fmaxf(0.f, fmaf(lo.w, sl.w, fl.w)));
        float v4 = rna_tf32(fmaxf(0.f, fmaf(hi.x, sh.x, fh.x)));
        float v5 = rna_tf32(fmaxf(0.f, fmaf(hi.y, sh.y, fh.y)));
        float v6 = rna_tf32(fmaxf(0.f, fmaf(hi.z, sh.z, fh.z)));
        float v7 = rna_tf32(fmaxf(0.f, fmaf(hi.w, sh.w, fh.w)));
        float4 o0, o1;
        o0.x = v0; o0.y = v4; o0.z = v1; o0.w = v5;
        o1.x = v2; o1.y = v6; o1.z = v3; o1.w = v7;
        ((float4*)out)[2 * i]     = o0;
        ((float4*)out)[2 * i + 1] = o1;
    }
}

__global__ void softmax_kernel(const float* __restrict__ logits,
                               float* __restrict__ probs, int M, int N) {
    int row  = blockIdx.x * (blockDim.x / 32) + threadIdx.x / 32;
    int lane = threadIdx.x & 31;
    if (row >= M) return;
    const float* lr = logits + (size_t)row * N;
    float v[3], mx = -1e30f;
#pragma unroll
    for (int j = 0; j < 3; j++) {
        int c = lane + j * 32;
        v[j] = (c < N) ? lr[c] : -1e30f;
        mx = fmaxf(mx, v[j]);
    }
#pragma unroll
    for (int o = 16; o; o >>= 1) mx = fmaxf(mx, __shfl_xor_sync(0xFFFFFFFFu, mx, o));
    float s = 0.f;
#pragma unroll
    for (int j = 0; j < 3; j++) {
        int c = lane + j * 32;
        v[j] = (c < N) ? expf(v[j] - mx) : 0.f;
        s += v[j];
    }
#pragma unroll
    for (int o = 16; o; o >>= 1) s += __shfl_xor_sync(0xFFFFFFFFu, s, o);
    float inv = 1.0f / s;
#pragma unroll
    for (int j = 0; j < 3; j++) {
        int c = lane + j * 32;
        if (c < N) probs[(size_t)row * N + c] = v[j] * inv;
    }
}

// ---------------------------------------------------------------------------
typedef CUresult (*EncodeTiledFn)(CUtensorMap*, CUtensorMapDataType, cuuint32_t,
                                  void*, const cuuint64_t*, const cuuint64_t*,
                                  const cuuint32_t*, const cuuint32_t*,
                                  CUtensorMapInterleave, CUtensorMapSwizzle,
                                  CUtensorMapL2promotion, CUtensorMapFloatOOBfill);

static void make_map2d(EncodeTiledFn enc, CUtensorMap* m, void* ptr,
                       uint64_t kdim, uint64_t rows) {
    cuuint64_t dims[2]    = {kdim, rows};
    cuuint64_t strides[1] = {kdim * 4};
    cuuint32_t box[2]     = {LDT, 128};
    cuuint32_t estr[2]    = {1, 1};
    enc(m, CU_TENSOR_MAP_DATA_TYPE_FLOAT32, 2, ptr, dims, strides, box, estr,
        CU_TENSOR_MAP_INTERLEAVE_NONE, CU_TENSOR_MAP_SWIZZLE_NONE,
        CU_TENSOR_MAP_L2_PROMOTION_L2_128B, CU_TENSOR_MAP_FLOAT_OOB_FILL_NONE);
}

extern "C" void kernel_launch(void* const* d_in, const int* in_sizes, int n_in,
                              void* d_out, int out_size) {
    const float* pooled   = (const float*)d_in[0];
    const float* w1       = (const float*)d_in[1];
    const float* b1       = (const float*)d_in[2];
    const float* gamma1   = (const float*)d_in[3];
    const float* beta1    = (const float*)d_in[4];
    const float* w2       = (const float*)d_in[5];
    const float* b2       = (const float*)d_in[6];
    const float* gamma2   = (const float*)d_in[7];
    const float* beta2    = (const float*)d_in[8];
    const float* w_logits = (const float*)d_in[9];
    const float* b_logits = (const float*)d_in[10];
    const float* w_delta  = (const float*)d_in[11];
    const float* b_delta  = (const float*)d_in[12];

    float* out        = (float*)d_out;
    float* out_logits = out;
    float* out_probs  = out + N_ROI * NCLS;
    float* out_deltas = out + 2 * N_ROI * NCLS;

    float *Ap, *W1t, *W2t, *Wht, *bh, *x1, *x1p, *x2, *x2p, *scale, *shift;
    cudaGetSymbolAddress((void**)&Ap,    g_Ap);
    cudaGetSymbolAddress((void**)&W1t,   g_W1t);
    cudaGetSymbolAddress((void**)&W2t,   g_W2t);
    cudaGetSymbolAddress((void**)&Wht,   g_Wht);
    cudaGetSymbolAddress((void**)&bh,    g_bh);
    cudaGetSymbolAddress((void**)&x1,    g_x1);
    cudaGetSymbolAddress((void**)&x1p,   g_x1p);
    cudaGetSymbolAddress((void**)&x2,    g_x2);
    cudaGetSymbolAddress((void**)&x2p,   g_x2p);
    cudaGetSymbolAddress((void**)&scale, g_scale);
    cudaGetSymbolAddress((void**)&shift, g_shift);

    EncodeTiledFn enc = nullptr;
#if CUDART_VERSION >= 12000
    cudaDriverEntryPointQueryResult qr;
    cudaGetDriverEntryPoint("cuTensorMapEncodeTiled", (void**)&enc,
                            cudaEnableDefault, &qr);
#else
    cudaGetDriverEntryPoint("cuTensorMapEncodeTiled", (void**)&enc, cudaEnableDefault);
#endif

    CUtensorMap mA1, mB1, mA2, mB2, mA3, mB3;
    make_map2d(enc, &mA1, Ap,  K1,  N_ROI);
    make_map2d(enc, &mB1, W1t, K1,  HID);
    make_map2d(enc, &mA2, x1p, HID, N_ROI);
    make_map2d(enc, &mB2, W2t, HID, HID);
    make_map2d(enc, &mA3, x2p, HID, N_ROI);
    make_map2d(enc, &mB3, Wht, HID, NHEAD);

    cudaFuncSetAttribute(gemm_tf32_tma, cudaFuncAttributeMaxDynamicSharedMemorySize, SMEM_TOT);

    // prep: 3 launches so GEMM1 is launch #4 (the one ncu profiles)
    int n8A = N_ROI * K1 / 8;
    cvt_rna_permute8<<<(n8A + 255) / 256, 256>>>(pooled, Ap, n8A);                   // 1
    prep_w12<<<W1_BLKS + W2_BLKS, dim3(32, 8)>>>(w1, w2, W1t, W2t);                  // 2
    prep_heads<<<32 * 13, dim3(32, 8)>>>(w_logits, w_delta, Wht,
                                         b_logits, b_delta, bh);                     // 3

    const int n8x = N_ROI * HID / 8;
    dim3 bn_block(32, 8);
    dim3 g1(HID / TN, (N_ROI + TM - 1) / TM);    // (8, 16)

    gemm_tf32_tma<<<g1, NTHREADS, SMEM_TOT>>>(mA1, mB1, b1, x1, nullptr, nullptr,
                                              N_ROI, K1, HID);                       // 4 (profiled)
    bn_stats_kernel<<<HID / 32, bn_block>>>(x1, gamma1, beta1, scale, shift, N_ROI, HID);
    bn_relu_rna_permute8<<<(n8x + 255) / 256, 256>>>(x1, x1p, scale, shift, n8x, HID);

    gemm_tf32_tma<<<g1, NTHREADS, SMEM_TOT>>>(mA2, mB2, b2, x2, nullptr, nullptr,
                                              N_ROI, HID, HID);
    bn_stats_kernel<<<HID / 32, bn_block>>>(x2, gamma2, beta2, scale, shift, N_ROI, HID);
    bn_relu_rna_permute8<<<(n8x + 255) / 256, 256>>>(x2, x2p, scale, shift, n8x, HID);

    dim3 gh(NHPAD / TN, (N_ROI + TM - 1) / TM);  // (4, 16)
    gemm_tf32_tma<<<gh, NTHREADS, SMEM_TOT>>>(mA3, mB3, bh, nullptr,
                                              out_logits, out_deltas, N_ROI, HID, NHPAD);
    softmax_kernel<<<(N_ROI + 7) / 8, 256>>>(out_logits, out_probs, N_ROI, NCLS);
}

// round 17
// speedup vs baseline: 1.2033x; 1.0037x over previous
#include <cuda_runtime.h>
#include <cuda.h>
#include <cstdint>

// ---------------------------------------------------------------------------
// BBoxHead via manual tf32 mma.sync GEMMs, TMA-fed, warp-specialized.
// CTA 128x128, 8 consumer warps (32x64) + 1 TMA producer, 4-stage pipeline.
// sigma-trick: NO k-permutation anywhere. LDS.64 at 2t puts k={2t,2t+1} in
// slots (t,0),(t,1) of BOTH operands -> valid bijective k-remap, exact result.
// A rna'd IN-REGISTER in the mainloop (B pre-rna'd in weight prep).
// Batched ks double-buffer: load ks+1 batch, then cvt+MMA ks.
// Heads GEMM writes logits/deltas directly (scatter fused).
// ---------------------------------------------------------------------------

#define N_ROI  2000
#define K1     12544
#define HID    1024
#define NCLS   81
#define NDEL   324
#define NHEAD  405
#define NHPAD  512
#define BN_EPS 1e-3f

__device__ float g_W1t [HID * K1];
__device__ float g_W2t [HID * HID];
__device__ float g_Wht [NHPAD * HID];
__device__ float g_bh  [NHPAD];
__device__ float g_x1  [2048 * HID];
__device__ float g_x2  [2048 * HID];
__device__ float g_scale[HID];
__device__ float g_shift[HID];

// ---------------------------------------------------------------------------
__device__ __forceinline__ uint32_t smem_u32(const void* p) {
    uint32_t a;
    asm("{ .reg .u64 t; cvta.to.shared.u64 t, %1; cvt.u32.u64 %0, t; }" : "=r"(a) : "l"(p));
    return a;
}
__device__ __forceinline__ float rna_tf32(float x) {
    uint32_t r;
    asm("cvt.rna.tf32.f32 %0, %1;" : "=r"(r) : "f"(x));
    return __uint_as_float(r);
}
__device__ __forceinline__ uint32_t rna_bits(uint32_t x) {
    return __float_as_uint(rna_tf32(__uint_as_float(x)));
}

#define MBAR_INIT(a, c)      asm volatile("mbarrier.init.shared.b64 [%0], %1;" :: "r"(a), "r"(c) : "memory")
#define MBAR_EXPECT_TX(a, b) asm volatile("mbarrier.arrive.expect_tx.shared.b64 _, [%0], %1;" :: "r"(a), "r"(b) : "memory")
#define MBAR_ARRIVE(a)       asm volatile("mbarrier.arrive.shared.b64 _, [%0];" :: "r"(a) : "memory")
#define MBAR_WAIT(a, ph) do {                                                     \
    uint32_t _m = (a); uint32_t _p = (ph);                                        \
    asm volatile("{\n\t.reg .pred P;\n\t"                                         \
        "WL_%=:\n\t"                                                              \
        "mbarrier.try_wait.parity.acquire.cta.shared::cta.b64 P, [%0], %1, 0x989680;\n\t" \
        "@P bra.uni WD_%=;\n\t"                                                   \
        "bra.uni WL_%=;\n\t"                                                      \
        "WD_%=:\n\t}" :: "r"(_m), "r"(_p) : "memory");                            \
} while (0)

#define TMA_LOAD_2D(saddr, mp, cx, cy, mb)                                        \
    asm volatile("cp.async.bulk.tensor.2d.shared::cta.global.tile.mbarrier::complete_tx::bytes " \
                 "[%0], [%1, {%2, %3}], [%4];"                                    \
                 :: "r"(saddr), "l"(mp), "r"(cx), "r"(cy), "r"(mb) : "memory")

#define LD2O(r0, r1, base, off)                                                   \
    asm volatile("ld.shared.v2.b32 {%0,%1}, [%2+%3];"                             \
        : "=r"(r0), "=r"(r1) : "r"(base), "n"(off))

#define ST2(addr, v0, v1)                                                         \
    asm volatile("st.shared.v2.f32 [%0], {%1,%2};" :: "r"(addr), "f"(v0), "f"(v1) : "memory")

#define MMA(cr, A0, A1, A2, A3, B0, B1)                                           \
    asm volatile("mma.sync.aligned.m16n8k8.row.col.f32.tf32.tf32.f32 "            \
        "{%0,%1,%2,%3}, {%4,%5,%6,%7}, {%8,%9}, {%0,%1,%2,%3};"                   \
        : "+f"((cr)[0]), "+f"((cr)[1]), "+f"((cr)[2]), "+f"((cr)[3])              \
        : "r"(A0), "r"(A1), "r"(A2), "r"(A3), "r"(B0), "r"(B1))

// ---------------------------------------------------------------------------
#define LDT      40
#define TM       128
#define TN       128
#define TILE_A   (TM * LDT * 4)                   // 20480
#define STAGE_B  (2 * TILE_A)                     // 40960
#define NSTAGE   4
#define SM_TILE0 1024
#define SMEM_TOT (SM_TILE0 + NSTAGE * STAGE_B)    // 164864
#define TXBYTES  STAGE_B
#define LDE      132
#define NTHREADS 288

// batched loads for one ks-step into buffer d (immediate offsets, no IADDs)
#define KS_LOAD(ks, d)                                                            \
    do {                                                                          \
        LD2O(Ar[d][0], Ar[d][2], sA, (ks) * 32);                                  \
        LD2O(Ar[d][1], Ar[d][3], sA, 8  * LDT * 4 + (ks) * 32);                   \
        LD2O(Ar[d][4], Ar[d][6], sA, 16 * LDT * 4 + (ks) * 32);                   \
        LD2O(Ar[d][5], Ar[d][7], sA, 24 * LDT * 4 + (ks) * 32);                   \
        LD2O(Br0[d][0], Br1[d][0], sB, 0 * 8 * LDT * 4 + (ks) * 32);              \
        LD2O(Br0[d][1], Br1[d][1], sB, 1 * 8 * LDT * 4 + (ks) * 32);              \
        LD2O(Br0[d][2], Br1[d][2], sB, 2 * 8 * LDT * 4 + (ks) * 32);              \
        LD2O(Br0[d][3], Br1[d][3], sB, 3 * 8 * LDT * 4 + (ks) * 32);              \
        LD2O(Br0[d][4], Br1[d][4], sB, 4 * 8 * LDT * 4 + (ks) * 32);              \
        LD2O(Br0[d][5], Br1[d][5], sB, 5 * 8 * LDT * 4 + (ks) * 32);              \
        LD2O(Br0[d][6], Br1[d][6], sB, 6 * 8 * LDT * 4 + (ks) * 32);              \
        LD2O(Br0[d][7], Br1[d][7], sB, 7 * 8 * LDT * 4 + (ks) * 32);              \
    } while (0)

// rna-round the A fragments of buffer d (B pre-rounded in prep)
#define KS_CVT(d)                                                                 \
    do {                                                                          \
        Ar[d][0] = rna_bits(Ar[d][0]); Ar[d][1] = rna_bits(Ar[d][1]);             \
        Ar[d][2] = rna_bits(Ar[d][2]); Ar[d][3] = rna_bits(Ar[d][3]);             \
        Ar[d][4] = rna_bits(Ar[d][4]); Ar[d][5] = rna_bits(Ar[d][5]);             \
        Ar[d][6] = rna_bits(Ar[d][6]); Ar[d][7] = rna_bits(Ar[d][7]);             \
    } while (0)

#define KS_MMA(d)                                                                 \
    do {                                                                          \
        MMA(c0[0], Ar[d][0], Ar[d][1], Ar[d][2], Ar[d][3], Br0[d][0], Br1[d][0]); \
        MMA(c0[1], Ar[d][0], Ar[d][1], Ar[d][2], Ar[d][3], Br0[d][1], Br1[d][1]); \
        MMA(c0[2], Ar[d][0], Ar[d][1], Ar[d][2], Ar[d][3], Br0[d][2], Br1[d][2]); \
        MMA(c0[3], Ar[d][0], Ar[d][1], Ar[d][2], Ar[d][3], Br0[d][3], Br1[d][3]); \
        MMA(c0[4], Ar[d][0], Ar[d][1], Ar[d][2], Ar[d][3], Br0[d][4], Br1[d][4]); \
        MMA(c0[5], Ar[d][0], Ar[d][1], Ar[d][2], Ar[d][3], Br0[d][5], Br1[d][5]); \
        MMA(c0[6], Ar[d][0], Ar[d][1], Ar[d][2], Ar[d][3], Br0[d][6], Br1[d][6]); \
        MMA(c0[7], Ar[d][0], Ar[d][1], Ar[d][2], Ar[d][3], Br0[d][7], Br1[d][7]); \
        MMA(c1[0], Ar[d][4], Ar[d][5], Ar[d][6], Ar[d][7], Br0[d][0], Br1[d][0]); \
        MMA(c1[1], Ar[d][4], Ar[d][5], Ar[d][6], Ar[d][7], Br0[d][1], Br1[d][1]); \
        MMA(c1[2], Ar[d][4], Ar[d][5], Ar[d][6], Ar[d][7], Br0[d][2], Br1[d][2]); \
        MMA(c1[3], Ar[d][4], Ar[d][5], Ar[d][6], Ar[d][7], Br0[d][3], Br1[d][3]); \
        MMA(c1[4], Ar[d][4], Ar[d][5], Ar[d][6], Ar[d][7], Br0[d][4], Br1[d][4]); \
        MMA(c1[5], Ar[d][4], Ar[d][5], Ar[d][6], Ar[d][7], Br0[d][5], Br1[d][5]); \
        MMA(c1[6], Ar[d][4], Ar[d][5], Ar[d][6], Ar[d][7], Br0[d][6], Br1[d][6]); \
        MMA(c1[7], Ar[d][4], Ar[d][5], Ar[d][6], Ar[d][7], Br0[d][7], Br1[d][7]); \
    } while (0)

__global__ __launch_bounds__(NTHREADS)
void gemm_tf32_tma(const __grid_constant__ CUtensorMap mapA,
                   const __grid_constant__ CUtensorMap mapB,
                   const float* __restrict__ bias, float* __restrict__ C,
                   float* __restrict__ hd_logits, float* __restrict__ hd_deltas,
                   int M, int K, int ldC) {
    extern __shared__ float smem_f[];
    const uint32_t sb = smem_u32(smem_f);
    const int tid  = threadIdx.x;
    const int wid  = tid >> 5;
    const int lane = tid & 31;
    const int row0 = blockIdx.y * TM;
    const int col0 = blockIdx.x * TN;
    const int NK = K / 32;

    if (tid == 0) {
#pragma unroll
        for (int s = 0; s < NSTAGE; s++) {
            MBAR_INIT(sb + s * 16,     1);
            MBAR_INIT(sb + s * 16 + 8, 8);
        }
    }
    __syncthreads();

    const int warp_m = wid & 3;
    const int warp_n = wid >> 2;
    const int g = lane >> 2;
    const int t = lane & 3;

    float c0[8][4], c1[8][4];

    if (wid == 8) {
        if (lane == 0) {
            int s = 0, ph = 1;
            for (int i = 0; i < NK; i++) {
                MBAR_WAIT(sb + s * 16 + 8, ph);
                uint32_t st = sb + SM_TILE0 + s * STAGE_B;
                MBAR_EXPECT_TX(sb + s * 16, TXBYTES);
                TMA_LOAD_2D(st,          &mapA, i * 32, row0, sb + s * 16);
                TMA_LOAD_2D(st + TILE_A, &mapB, i * 32, col0, sb + s * 16);
                if (++s == NSTAGE) { s = 0; ph ^= 1; }
            }
        }
    } else {
#pragma unroll
        for (int nj = 0; nj < 8; nj++)
#pragma unroll
            for (int r = 0; r < 4; r++) { c0[nj][r] = 0.f; c1[nj][r] = 0.f; }

        const uint32_t aLane = ((warp_m * 32 + g) * LDT + 2 * t) * 4;
        const uint32_t bLane = ((warp_n * 64 + g) * LDT + 2 * t) * 4;

        uint32_t Ar[2][8], Br0[2][8], Br1[2][8];

        int s = 0, ph = 0;
        for (int i = 0; i < NK; i++) {
            MBAR_WAIT(sb + s * 16, ph);
            const uint32_t sA = sb + SM_TILE0 + s * STAGE_B + aLane;
            const uint32_t sB = sb + SM_TILE0 + s * STAGE_B + TILE_A + bLane;

            // software-pipelined ks steps: load ks+1, cvt+mma ks
            KS_LOAD(0, 0);
            KS_LOAD(1, 1); KS_CVT(0); KS_MMA(0);
            KS_LOAD(2, 0); KS_CVT(1); KS_MMA(1);
            KS_LOAD(3, 1); KS_CVT(0); KS_MMA(0);
                           KS_CVT(1); KS_MMA(1);

            if (lane == 0) MBAR_ARRIVE(sb + s * 16 + 8);
            if (++s == NSTAGE) { s = 0; ph ^= 1; }
        }
    }
    __syncthreads();

    if (wid != 8) {
        const uint32_t eb = sb;
#pragma unroll
        for (int nj = 0; nj < 8; nj++) {
            uint32_t colb = (warp_n * 64 + nj * 8 + 2 * t) * 4;
            uint32_t r0 = (warp_m * 32 + g) * LDE * 4;
            ST2(eb + r0 + colb,                c0[nj][0], c0[nj][1]);
            ST2(eb + r0 + 8  * LDE * 4 + colb, c0[nj][2], c0[nj][3]);
            ST2(eb + r0 + 16 * LDE * 4 + colb, c1[nj][0], c1[nj][1]);
            ST2(eb + r0 + 24 * LDE * 4 + colb, c1[nj][2], c1[nj][3]);
        }
    }
    __syncthreads();

    const float* esm = smem_f;
    if (hd_deltas == nullptr) {
#pragma unroll 2
        for (int e = tid; e < TM * 32; e += NTHREADS) {
            int r  = e >> 5;
            int c4 = (e & 31) * 4;
            int gr = row0 + r;
            if (gr < M) {
                const float* sp = esm + r * LDE + c4;
                float4 v;
                v.x = sp[0] + bias[col0 + c4 + 0];
                v.y = sp[1] + bias[col0 + c4 + 1];
                v.z = sp[2] + bias[col0 + c4 + 2];
                v.w = sp[3] + bias[col0 + c4 + 3];
                *(float4*)&C[(size_t)gr * ldC + col0 + c4] = v;
            }
        }
    } else {
        for (int e = tid; e < TM * TN; e += NTHREADS) {
            int r  = e >> 7;
            int c  = e & 127;
            int gr = row0 + r;
            int gc = col0 + c;
            if (gr < M && gc < NHEAD) {
                float v = esm[r * LDE + c] + bias[gc];
                if (gc < NCLS) hd_logits[(size_t)gr * NCLS + gc] = v;
                else           hd_deltas[(size_t)gr * NDEL + (gc - NCLS)] = v;
            }
        }
    }
}

// ---------------------------------------------------------------------------
// Prep kernels (weight transpose + rna; natural k order, no permutation)
// ---------------------------------------------------------------------------
#define W1_BLKS  (392 * 32)
#define W2_BLKS  (32 * 32)
__global__ void prep_w12(const float* __restrict__ w1, const float* __restrict__ w2,
                         float* __restrict__ W1t, float* __restrict__ W2t) {
    __shared__ float tsm[32][33];
    int b = blockIdx.x;
    int x = threadIdx.x, y = threadIdx.y;
    if (b < W1_BLKS) {
        int kblk = b % 392, nblk = b / 392;
        int k0 = kblk * 32, n0 = nblk * 32;
#pragma unroll
        for (int yy = y; yy < 32; yy += 8)
            tsm[yy][x] = w1[(size_t)(k0 + yy) * HID + n0 + x];
        __syncthreads();
#pragma unroll
        for (int yy = y; yy < 32; yy += 8)
            W1t[(size_t)(n0 + yy) * K1 + k0 + x] = rna_tf32(tsm[x][yy]);
    } else {
        int b2 = b - W1_BLKS;
        int kblk = b2 % 32, nblk = b2 / 32;
        int k0 = kblk * 32, n0 = nblk * 32;
#pragma unroll
        for (int yy = y; yy < 32; yy += 8)
            tsm[yy][x] = w2[(size_t)(k0 + yy) * HID + n0 + x];
        __syncthreads();
#pragma unroll
        for (int yy = y; yy < 32; yy += 8)
            W2t[(size_t)(n0 + yy) * HID + k0 + x] = rna_tf32(tsm[x][yy]);
    }
}

__global__ void prep_heads(const float* __restrict__ wl, const float* __restrict__ wd,
                           float* __restrict__ Wht) {
    __shared__ float tsm[32][33];
    int kblk = blockIdx.x % 32, nblk = blockIdx.x / 32;
    int k0 = kblk * 32, n0 = nblk * 32;
    int x = threadIdx.x, y = threadIdx.y;
#pragma unroll
    for (int yy = y; yy < 32; yy += 8) {
        int k = k0 + yy, n = n0 + x;
        float v = 0.f;
        if (n < NHEAD)
            v = (n < NCLS) ? wl[(size_t)k * NCLS + n]
                           : wd[(size_t)k * NDEL + (n - NCLS)];
        tsm[yy][x] = v;
    }
    __syncthreads();
#pragma unroll
    for (int yy = y; yy < 32; yy += 8) {
        int n = n0 + yy;
        if (n < NHEAD)
            Wht[(size_t)n * HID + k0 + x] = rna_tf32(tsm[x][yy]);
    }
}

__global__ void bh_init(const float* __restrict__ bl, const float* __restrict__ bd,
                        float* __restrict__ bh) {
    int i = blockIdx.x * blockDim.x + threadIdx.x;
    if (i < NHPAD)
        bh[i] = (i < NCLS) ? bl[i] : (i < NHEAD ? bd[i - NCLS] : 0.f);
}

// ---------------------------------------------------------------------------
// BN / epilogue
// ---------------------------------------------------------------------------
__global__ void bn_stats_kernel(const float* __restrict__ x,
                                const float* __restrict__ gamma,
                                const float* __restrict__ beta,
                                float* __restrict__ scale, float* __restrict__ shift,
                                int M, int N) {
    int col = blockIdx.x * 32 + threadIdx.x;
    float s = 0.f, sq = 0.f;
    for (int r = threadIdx.y; r < M; r += blockDim.y) {
        float v = x[(size_t)r * N + col];
        s += v; sq += v * v;
    }
    __shared__ float ss[8][32], sg[8][32];
    ss[threadIdx.y][threadIdx.x] = s;
    sg[threadIdx.y][threadIdx.x] = sq;
    __syncthreads();
    if (threadIdx.y == 0) {
#pragma unroll
        for (int i = 1; i < 8; i++) { s += ss[i][threadIdx.x]; sq += sg[i][threadIdx.x]; }
        float mean = s / (float)M;
        float var  = sq / (float)M - mean * mean;
        float sc   = gamma[col] * rsqrtf(var + BN_EPS);
        scale[col] = sc;
        shift[col] = beta[col] - mean * sc;
    }
}

// in-place vectorized BN-ReLU (rna applied later in-register by the GEMM)
__global__ void bn_relu8(float* __restrict__ x,
                         const float* __restrict__ scale,
                         const float* __restrict__ shift, int n8, int N) {
    int i = blockIdx.x * blockDim.x + threadIdx.x;
    if (i < n8) {
        int c0 = (i * 8) & (N - 1);
        float4 lo = ((const float4*)x)[2 * i];
        float4 hi = ((const float4*)x)[2 * i + 1];
        float4 sl = ((const float4*)scale)[c0 / 4];
        float4 sh = ((const float4*)scale)[c0 / 4 + 1];
        float4 fl = ((const float4*)shift)[c0 / 4];
        float4 fh = ((const float4*)shift)[c0 / 4 + 1];
        float4 o0, o1;
        o0.x = fmaxf(0.f, fmaf(lo.x, sl.x, fl.x));
        o0.y = fmaxf(0.f, fmaf(lo.y, sl.y, fl.y));
        o0.z = fmaxf(0.f, fmaf(lo.z, sl.z, fl.z));
        o0.w = fmaxf(0.f, fmaf(lo.w, sl.w, fl.w));
        o1.x = fmaxf(0.f, fmaf(hi.x, sh.x, fh.x));
        o1.y = fmaxf(0.f, fmaf(hi.y, sh.y, fh.y));
        o1.z = fmaxf(0.f, fmaf(hi.z, sh.z, fh.z));
        o1.w = fmaxf(0.f, fmaf(hi.w, sh.w, fh.w));
        ((float4*)x)[2 * i]     = o0;
        ((float4*)x)[2 * i + 1] = o1;
    }
}

__global__ void softmax_kernel(const float* __restrict__ logits,
                               float* __restrict__ probs, int M, int N) {
    int row  = blockIdx.x * (blockDim.x / 32) + threadIdx.x / 32;
    int lane = threadIdx.x & 31;
    if (row >= M) return;
    const float* lr = logits + (size_t)row * N;
    float v[3], mx = -1e30f;
#pragma unroll
    for (int j = 0; j < 3; j++) {
        int c = lane + j * 32;
        v[j] = (c < N) ? lr[c] : -1e30f;
        mx = fmaxf(mx, v[j]);
    }
#pragma unroll
    for (int o = 16; o; o >>= 1) mx = fmaxf(mx, __shfl_xor_sync(0xFFFFFFFFu, mx, o));
    float s = 0.f;
#pragma unroll
    for (int j = 0; j < 3; j++) {
        int c = lane + j * 32;
        v[j] = (c < N) ? expf(v[j] - mx) : 0.f;
        s += v[j];
    }
#pragma unroll
    for (int o = 16; o; o >>= 1) s += __shfl_xor_sync(0xFFFFFFFFu, s, o);
    float inv = 1.0f / s;
#pragma unroll
    for (int j = 0; j < 3; j++) {
        int c = lane + j * 32;
        if (c < N) probs[(size_t)row * N + c] = v[j] * inv;
    }
}

// ---------------------------------------------------------------------------
typedef CUresult (*EncodeTiledFn)(CUtensorMap*, CUtensorMapDataType, cuuint32_t,
                                  void*, const cuuint64_t*, const cuuint64_t*,
                                  const cuuint32_t*, const cuuint32_t*,
                                  CUtensorMapInterleave, CUtensorMapSwizzle,
                                  CUtensorMapL2promotion, CUtensorMapFloatOOBfill);

static void make_map2d(EncodeTiledFn enc, CUtensorMap* m, void* ptr,
                       uint64_t kdim, uint64_t rows) {
    cuuint64_t dims[2]    = {kdim, rows};
    cuuint64_t strides[1] = {kdim * 4};
    cuuint32_t box[2]     = {LDT, 128};
    cuuint32_t estr[2]    = {1, 1};
    enc(m, CU_TENSOR_MAP_DATA_TYPE_FLOAT32, 2, ptr, dims, strides, box, estr,
        CU_TENSOR_MAP_INTERLEAVE_NONE, CU_TENSOR_MAP_SWIZZLE_NONE,
        CU_TENSOR_MAP_L2_PROMOTION_L2_128B, CU_TENSOR_MAP_FLOAT_OOB_FILL_NONE);
}

extern "C" void kernel_launch(void* const* d_in, const int* in_sizes, int n_in,
                              void* d_out, int out_size) {
    const float* pooled   = (const float*)d_in[0];
    const float* w1       = (const float*)d_in[1];
    const float* b1       = (const float*)d_in[2];
    const float* gamma1   = (const float*)d_in[3];
    const float* beta1    = (const float*)d_in[4];
    const float* w2       = (const float*)d_in[5];
    const float* b2       = (const float*)d_in[6];
    const float* gamma2   = (const float*)d_in[7];
    const float* beta2    = (const float*)d_in[8];
    const float* w_logits = (const float*)d_in[9];
    const float* b_logits = (const float*)d_in[10];
    const float* w_delta  = (const float*)d_in[11];
    const float* b_delta  = (const float*)d_in[12];

    float* out        = (float*)d_out;
    float* out_logits = out;
    float* out_probs  = out + N_ROI * NCLS;
    float* out_deltas = out + 2 * N_ROI * NCLS;

    float *W1t, *W2t, *Wht, *bh, *x1, *x2, *scale, *shift;
    cudaGetSymbolAddress((void**)&W1t,   g_W1t);
    cudaGetSymbolAddress((void**)&W2t,   g_W2t);
    cudaGetSymbolAddress((void**)&Wht,   g_Wht);
    cudaGetSymbolAddress((void**)&bh,    g_bh);
    cudaGetSymbolAddress((void**)&x1,    g_x1);
    cudaGetSymbolAddress((void**)&x2,    g_x2);
    cudaGetSymbolAddress((void**)&scale, g_scale);
    cudaGetSymbolAddress((void**)&shift, g_shift);

    EncodeTiledFn enc = nullptr;
#if CUDART_VERSION >= 12000
    cudaDriverEntryPointQueryResult qr;
    cudaGetDriverEntryPoint("cuTensorMapEncodeTiled", (void**)&enc,
                            cudaEnableDefault, &qr);
#else
    cudaGetDriverEntryPoint("cuTensorMapEncodeTiled", (void**)&enc, cudaEnableDefault);
#endif

    CUtensorMap mA1, mB1, mA2, mB2, mA3, mB3;
    make_map2d(enc, &mA1, (void*)pooled, K1,  N_ROI);
    make_map2d(enc, &mB1, W1t, K1,  HID);
    make_map2d(enc, &mA2, x1,  HID, N_ROI);
    make_map2d(enc, &mB2, W2t, HID, HID);
    make_map2d(enc, &mA3, x2,  HID, N_ROI);
    make_map2d(enc, &mB3, Wht, HID, NHEAD);

    cudaFuncSetAttribute(gemm_tf32_tma, cudaFuncAttributeMaxDynamicSharedMemorySize, SMEM_TOT);

    // prep: 3 launches so GEMM1 is launch #4 (the one ncu profiles)
    prep_w12<<<W1_BLKS + W2_BLKS, dim3(32, 8)>>>(w1, w2, W1t, W2t);                  // 1
    prep_heads<<<32 * 13, dim3(32, 8)>>>(w_logits, w_delta, Wht);                    // 2
    bh_init<<<2, 256>>>(b_logits, b_delta, bh);                                      // 3

    const int n8x = N_ROI * HID / 8;
    dim3 bn_block(32, 8);
    dim3 g1(HID / TN, (N_ROI + TM - 1) / TM);    // (8, 16)

    gemm_tf32_tma<<<g1, NTHREADS, SMEM_TOT>>>(mA1, mB1, b1, x1, nullptr, nullptr,
                                              N_ROI, K1, HID);                       // 4 (profiled)
    bn_stats_kernel<<<HID / 32, bn_block>>>(x1, gamma1, beta1, scale, shift, N_ROI, HID);
    bn_relu8<<<(n8x + 255) / 256, 256>>>(x1, scale, shift, n8x, HID);

    gemm_tf32_tma<<<g1, NTHREADS, SMEM_TOT>>>(mA2, mB2, b2, x2, nullptr, nullptr,
                                              N_ROI, HID, HID);
    bn_stats_kernel<<<HID / 32, bn_block>>>(x2, gamma2, beta2, scale, shift, N_ROI, HID);
    bn_relu8<<<(n8x + 255) / 256, 256>>>(x2, scale, shift, n8x, HID);

    dim3 gh(NHPAD / TN, (N_ROI + TM - 1) / TM);  // (4, 16)
    gemm_tf32_tma<<<gh, NTHREADS, SMEM_TOT>>>(mA3, mB3, bh, nullptr,
                                              out_logits, out_deltas, N_ROI, HID, NHPAD);
    softmax_kernel<<<(N_ROI + 7) / 8, 256>>>(out_logits, out_probs, N_ROI, NCLS);
}